// round 8
// baseline (speedup 1.0000x reference)
#include <cuda_runtime.h>
#include <math.h>
#include <stdint.h>

#define Bn   16
#define Sn   512
#define Dn   1024
#define Hn   8
#define DHn  512
#define HDn  64
#define DFFn 4096
#define BSn  (Bn*Sn)   // 8192

// ---------------- scratch (static device globals; no allocation) ----------------
__device__ float g_q1[Bn*Hn*Sn*HDn];
__device__ float g_k1[Bn*Hn*Sn*HDn];   // stored transposed: (B,H,64,S)
__device__ float g_v1[Bn*Hn*Sn*HDn];
__device__ float g_q2[Bn*Hn*Sn*HDn];
__device__ float g_k2[Bn*Hn*Sn*HDn];   // transposed
__device__ float g_v2[Bn*Hn*Sn*HDn];
__device__ float g_av1[BSn*DHn];
__device__ float g_av2[BSn*DHn];
__device__ float g_attn[BSn*Dn];
__device__ float g_out1[BSn*Dn];
__device__ float g_hid[(size_t)BSn*DFFn];
__device__ float g_ffn[BSn*Dn];

__device__ __forceinline__ float gelu_f(float x){
    return 0.5f * x * (1.0f + erff(x * 0.70710678118654752440f));
}
__device__ __forceinline__ unsigned f2tf(float x){
    unsigned u; asm("cvt.rna.tf32.f32 %0, %1;" : "=r"(u) : "f"(x)); return u;
}

#define MMA_TF32(acc, af, bf) \
    asm volatile( \
        "mma.sync.aligned.m16n8k8.row.col.f32.tf32.tf32.f32 " \
        "{%0,%1,%2,%3}, {%4,%5,%6,%7}, {%8,%9}, {%0,%1,%2,%3};" \
        : "+f"((acc)[0]), "+f"((acc)[1]), "+f"((acc)[2]), "+f"((acc)[3]) \
        : "r"((af)[0]), "r"((af)[1]), "r"((af)[2]), "r"((af)[3]), \
          "r"((bf)[0]), "r"((bf)[1]))

// =================== double-buffered TF32 GEMM core (128x128x16, 256 thr) ===================
// One __syncthreads per K-slab: MMA(buf cur) overlaps STS(buf 1-cur).
#define PADA 20

__device__ __forceinline__ void gemm_core_db(
    const float* __restrict__ A, int lda,
    const float* __restrict__ Bw, int ldb,
    int K,
    unsigned (*As)[PADA],   // [2*128][PADA]
    unsigned (*Bs)[136],    // [2*16][136]
    float (&acc)[4][4][4])
{
    const int tid  = threadIdx.x;
    const int lane = tid & 31;
    const int warp = tid >> 5;
    const int wy = warp >> 2, wx = warp & 3;
    const int lg = lane >> 2, lt = lane & 3;

    const int arow = tid >> 2, akq = tid & 3;        // A: 2 rows per thread (it*64 offset on row)
    const int bkk = tid >> 5, bnq = tid & 31;        // B: 2 k-rows per thread

    float4 ra[2], rb[2];
    // prologue: slab 0 -> regs -> buf0
    #pragma unroll
    for (int it = 0; it < 2; it++) {
        ra[it] = *(const float4*)(A + (size_t)(arow + it*64)*lda + akq*4);
        rb[it] = *(const float4*)(Bw + (size_t)(bkk + it*8)*ldb + bnq*4);
    }
    #pragma unroll
    for (int it = 0; it < 2; it++) {
        uint4 t;
        t.x = f2tf(ra[it].x); t.y = f2tf(ra[it].y); t.z = f2tf(ra[it].z); t.w = f2tf(ra[it].w);
        *(uint4*)(&As[arow + it*64][akq*4]) = t;
        uint4 u;
        u.x = f2tf(rb[it].x); u.y = f2tf(rb[it].y); u.z = f2tf(rb[it].z); u.w = f2tf(rb[it].w);
        *(uint4*)(&Bs[bkk + it*8][bnq*4]) = u;
    }
    __syncthreads();

    const int nslab = K >> 4;
    for (int s = 0; s < nslab; s++) {
        const int cur = s & 1;
        const bool more = (s + 1 < nslab);

        // issue next slab's global loads (overlap with MMA below)
        if (more) {
            int k0 = (s + 1) << 4;
            #pragma unroll
            for (int it = 0; it < 2; it++) {
                ra[it] = *(const float4*)(A + (size_t)(arow + it*64)*lda + k0 + akq*4);
                rb[it] = *(const float4*)(Bw + (size_t)(k0 + bkk + it*8)*ldb + bnq*4);
            }
        }

        // MMA on buffer cur
        unsigned (*Ac)[PADA] = As + cur*128;
        unsigned (*Bc)[136]  = Bs + cur*16;
        #pragma unroll
        for (int ks = 0; ks < 2; ks++) {
            const int kb = ks*8;
            unsigned af[4][4], bf[4][2];
            #pragma unroll
            for (int fm = 0; fm < 4; fm++) {
                int rbw = wy*64 + fm*16 + lg;
                af[fm][0] = Ac[rbw  ][kb+lt];
                af[fm][1] = Ac[rbw+8][kb+lt];
                af[fm][2] = Ac[rbw  ][kb+4+lt];
                af[fm][3] = Ac[rbw+8][kb+4+lt];
            }
            #pragma unroll
            for (int fn = 0; fn < 4; fn++) {
                int cb = wx*32 + fn*8 + lg;
                bf[fn][0] = Bc[kb+lt  ][cb];
                bf[fn][1] = Bc[kb+4+lt][cb];
            }
            #pragma unroll
            for (int fm = 0; fm < 4; fm++)
                #pragma unroll
                for (int fn = 0; fn < 4; fn++)
                    MMA_TF32(acc[fm][fn], af[fm], bf[fn]);
        }

        // STS into the other buffer (overlaps MMA issue above)
        if (more) {
            unsigned (*An)[PADA] = As + (1-cur)*128;
            unsigned (*Bnx)[136] = Bs + (1-cur)*16;
            #pragma unroll
            for (int it = 0; it < 2; it++) {
                uint4 t;
                t.x = f2tf(ra[it].x); t.y = f2tf(ra[it].y); t.z = f2tf(ra[it].z); t.w = f2tf(ra[it].w);
                *(uint4*)(&An[arow + it*64][akq*4]) = t;
                uint4 u;
                u.x = f2tf(rb[it].x); u.y = f2tf(rb[it].y); u.z = f2tf(rb[it].z); u.w = f2tf(rb[it].w);
                *(uint4*)(&Bnx[bkk + it*8][bnq*4]) = u;
            }
        }
        __syncthreads();
    }
}

// =================== QKV: 6 batched GEMMs, scatter epilogue ===================
__global__ void __launch_bounds__(256,2) qkv_k(
    const float* __restrict__ x,
    const float* w0, const float* w1, const float* w2,
    const float* w3, const float* w4, const float* w5,
    const float* b0, const float* b1, const float* b2,
    const float* b3, const float* b4, const float* b5,
    float* o0, float* o1, float* o2, float* o3, float* o4, float* o5)
{
    __shared__ unsigned As[2*128][PADA];
    __shared__ unsigned Bs[2*16][136];

    const int z = blockIdx.z;
    const float* W; const float* bi; float* dst;
    switch (z) {
        case 0: W=w0; bi=b0; dst=o0; break;
        case 1: W=w1; bi=b1; dst=o1; break;
        case 2: W=w2; bi=b2; dst=o2; break;
        case 3: W=w3; bi=b3; dst=o3; break;
        case 4: W=w4; bi=b4; dst=o4; break;
        default:W=w5; bi=b5; dst=o5; break;
    }
    const int m0 = blockIdx.y*128, n0 = blockIdx.x*128;
    const float* A = x + (z>=3 ? DHn : 0) + (size_t)m0*Dn;
    const float* Bp = W + n0;

    float acc[4][4][4];
    #pragma unroll
    for (int i=0;i<4;i++) for (int j=0;j<4;j++) for (int r=0;r<4;r++) acc[i][j][r]=0.f;

    gemm_core_db(A, Dn, Bp, DHn, DHn, As, Bs, acc);

    const int lane = threadIdx.x & 31, warp = threadIdx.x >> 5;
    const int wy = warp >> 2, wx = warp & 3;
    const int lg = lane >> 2, lt = lane & 3;
    const bool isK = (z==1 || z==4);

    #pragma unroll
    for (int fm=0; fm<4; fm++){
        #pragma unroll
        for (int fn=0; fn<4; fn++){
            int r = wy*64 + fm*16 + lg;
            int c = wx*32 + fn*8 + lt*2;
            #pragma unroll
            for (int q=0; q<4; q++){
                int m = m0 + r + (q>=2 ? 8 : 0);
                int n = n0 + c + (q&1);
                float v = acc[fm][fn][q] + bi[n];
                int b = m>>9, s = m&511, h = n>>6, d = n&63;
                if (isK) dst[(((size_t)(b*8+h))*64 + d)*512 + s] = v;
                else     dst[(((size_t)(b*8+h))*512 + s)*64 + d] = v;
            }
        }
    }
}

// =================== fused attention: score + softmax + aw write + AV ===================
#define SLD 516   // sL row stride in floats

__global__ void __launch_bounds__(256,1) fattn_k(
    const float* __restrict__ q1, const float* __restrict__ k1, const float* __restrict__ v1,
    const float* __restrict__ q2, const float* __restrict__ k2, const float* __restrict__ v2,
    const float* __restrict__ mask, const float* __restrict__ adjoin, const float* __restrict__ dist,
    float* __restrict__ aw_l, float* __restrict__ aw_g,
    float* __restrict__ av1, float* __restrict__ av2)
{
    extern __shared__ char smem_raw[];
    float* sL = (float*)smem_raw;                                        // [64][SLD]
    unsigned (*sQ)[68]  = (unsigned(*)[68]) (smem_raw + 64*SLD*4);       // [64][68]
    unsigned (*sB)[136] = (unsigned(*)[136])(smem_raw + 64*SLD*4 + 64*68*4); // [2*16][136]

    const int tid = threadIdx.x, lane = tid & 31, warp = tid >> 5;
    const int lg = lane >> 2, lt = lane & 3;
    const int zi = blockIdx.y;
    const int sel = zi >> 7, zb = zi & 127;
    const int b = zb >> 3, h = zb & 7;
    const int m0 = blockIdx.x * 64;

    const float* q  = (sel ? q2 : q1) + (size_t)zb*Sn*HDn;
    const float* kT = (sel ? k2 : k1) + (size_t)zb*HDn*Sn;   // (64,512)
    const float* v  = (sel ? v2 : v1) + (size_t)zb*Sn*HDn;
    float* aw = (sel ? aw_g : aw_l) + (size_t)zb*Sn*Sn;
    float* av = sel ? av2 : av1;
    const float* extra = (sel ? dist : adjoin) + (size_t)b*Sn*Sn;
    const float* mrow  = mask + (size_t)b*Sn;

    // ---- Phase 1: Q tile (64x64) -> sQ as tf32 ----
    #pragma unroll
    for (int it = 0; it < 4; it++) {
        int l = tid + it*256;
        int row = l >> 4, dq = l & 15;
        float4 a = *(const float4*)(q + (size_t)(m0+row)*HDn + dq*4);
        uint4 t;
        t.x = f2tf(a.x); t.y = f2tf(a.y); t.z = f2tf(a.z); t.w = f2tf(a.w);
        *(uint4*)(&sQ[row][dq*4]) = t;
    }

    // ---- Phase 2: scores (64 x 512) -> sL ----
    {
        const int wy = warp >> 2, wx = warp & 3;   // 2 x 4 warp grid
        const int bkk = tid >> 5, bnq = tid & 31;
        for (int n0 = 0; n0 < 512; n0 += 128) {
            float acc[2][4][4];
            #pragma unroll
            for (int i=0;i<2;i++) for (int j=0;j<4;j++) for (int r=0;r<4;r++) acc[i][j][r]=0.f;

            float4 rk[2];
            // prologue: slab 0 -> buf0
            #pragma unroll
            for (int it = 0; it < 2; it++)
                rk[it] = *(const float4*)(kT + (size_t)(bkk + it*8)*Sn + n0 + bnq*4);
            #pragma unroll
            for (int it = 0; it < 2; it++) {
                uint4 t;
                t.x = f2tf(rk[it].x); t.y = f2tf(rk[it].y);
                t.z = f2tf(rk[it].z); t.w = f2tf(rk[it].w);
                *(uint4*)(&sB[bkk + it*8][bnq*4]) = t;
            }
            __syncthreads();

            for (int kc = 0; kc < 4; kc++) {
                const int cur = kc & 1;
                if (kc < 3) {
                    #pragma unroll
                    for (int it = 0; it < 2; it++)
                        rk[it] = *(const float4*)(kT + (size_t)(kc*16 + 16 + bkk + it*8)*Sn + n0 + bnq*4);
                }
                unsigned (*Bc)[136] = sB + cur*16;
                #pragma unroll
                for (int ks = 0; ks < 2; ks++) {
                    int kb = kc*16 + ks*8;      // sQ column
                    int sb = ks*8;              // Bc row
                    unsigned af[2][4], bf[4][2];
                    #pragma unroll
                    for (int fm = 0; fm < 2; fm++) {
                        int rb = wy*32 + fm*16 + lg;
                        af[fm][0] = sQ[rb  ][kb+lt];
                        af[fm][1] = sQ[rb+8][kb+lt];
                        af[fm][2] = sQ[rb  ][kb+4+lt];
                        af[fm][3] = sQ[rb+8][kb+4+lt];
                    }
                    #pragma unroll
                    for (int fn = 0; fn < 4; fn++) {
                        int cb = wx*32 + fn*8 + lg;
                        bf[fn][0] = Bc[sb+lt  ][cb];
                        bf[fn][1] = Bc[sb+4+lt][cb];
                    }
                    #pragma unroll
                    for (int fm = 0; fm < 2; fm++)
                        #pragma unroll
                        for (int fn = 0; fn < 4; fn++)
                            MMA_TF32(acc[fm][fn], af[fm], bf[fn]);
                }
                if (kc < 3) {
                    unsigned (*Bnx)[136] = sB + (1-cur)*16;
                    #pragma unroll
                    for (int it = 0; it < 2; it++) {
                        uint4 t;
                        t.x = f2tf(rk[it].x); t.y = f2tf(rk[it].y);
                        t.z = f2tf(rk[it].z); t.w = f2tf(rk[it].w);
                        *(uint4*)(&Bnx[bkk + it*8][bnq*4]) = t;
                    }
                }
                __syncthreads();
            }
            // epilogue: logits -> sL
            #pragma unroll
            for (int fm = 0; fm < 2; fm++) {
                #pragma unroll
                for (int fn = 0; fn < 4; fn++) {
                    #pragma unroll
                    for (int q4 = 0; q4 < 4; q4++) {
                        int r = wy*32 + fm*16 + lg + ((q4>=2) ? 8 : 0);
                        int c = wx*32 + fn*8 + lt*2 + (q4&1);
                        int j = n0 + c;
                        float s = acc[fm][fn][q4];
                        float logit;
                        if (sel == 0) {
                            logit = s*0.125f + mrow[j]*(-1.0e9f)
                                  + extra[(size_t)(m0+r)*Sn + j];
                        } else {
                            float w  = extra[(size_t)(m0+r)*Sn + j];
                            float rs = 3.7182818284590452f / (1.f + expf(1.f - w));
                            logit = fmaxf(s, 0.f)*rs*0.125f + mrow[j]*(-1.0e9f);
                        }
                        sL[r*SLD + j] = logit;
                    }
                }
            }
        }
    }
    __syncthreads();

    // ---- Phase 3: softmax per row (warp handles 8 rows); write aw ----
    for (int rr = 0; rr < 8; rr++) {
        int r = warp*8 + rr;
        float4* rowp = (float4*)(sL + (size_t)r*SLD);
        float4 rv[4];
        float lmax = -3.0e38f;
        #pragma unroll
        for (int it = 0; it < 4; it++) {
            float4 v4 = rowp[it*32 + lane];
            rv[it] = v4;
            lmax = fmaxf(lmax, fmaxf(fmaxf(v4.x, v4.y), fmaxf(v4.z, v4.w)));
        }
        #pragma unroll
        for (int o = 16; o > 0; o >>= 1)
            lmax = fmaxf(lmax, __shfl_xor_sync(0xffffffffu, lmax, o));
        float sum = 0.f;
        #pragma unroll
        for (int it = 0; it < 4; it++) {
            rv[it].x = expf(rv[it].x - lmax);
            rv[it].y = expf(rv[it].y - lmax);
            rv[it].z = expf(rv[it].z - lmax);
            rv[it].w = expf(rv[it].w - lmax);
            sum += rv[it].x + rv[it].y + rv[it].z + rv[it].w;
        }
        #pragma unroll
        for (int o = 16; o > 0; o >>= 1)
            sum += __shfl_xor_sync(0xffffffffu, sum, o);
        float inv = 1.f / sum;
        float4* awp = (float4*)(aw + (size_t)(m0+r)*Sn);
        #pragma unroll
        for (int it = 0; it < 4; it++) {
            rv[it].x *= inv; rv[it].y *= inv; rv[it].z *= inv; rv[it].w *= inv;
            rowp[it*32 + lane] = rv[it];
            awp[it*32 + lane]  = rv[it];
        }
    }
    __syncthreads();

    // ---- Phase 4: AV = probs(64x512) @ V(512x64) ----
    {
        const int wy4 = warp >> 1, wx4 = warp & 1;   // 4 x 2 warp grid
        const int vkk = tid >> 4, vdq = tid & 15;
        float acc2[4][4];
        #pragma unroll
        for (int j=0;j<4;j++) for (int r=0;r<4;r++) acc2[j][r]=0.f;

        float4 rvv;
        // prologue: slab 0 -> buf0
        rvv = *(const float4*)(v + (size_t)vkk*HDn + vdq*4);
        {
            uint4 t;
            t.x = f2tf(rvv.x); t.y = f2tf(rvv.y); t.z = f2tf(rvv.z); t.w = f2tf(rvv.w);
            *(uint4*)(&sB[vkk][vdq*4]) = t;
        }
        __syncthreads();

        for (int kc = 0; kc < 32; kc++) {
            const int cur = kc & 1;
            if (kc < 31)
                rvv = *(const float4*)(v + (size_t)(kc*16 + 16 + vkk)*HDn + vdq*4);

            unsigned (*Bc)[136] = sB + cur*16;
            #pragma unroll
            for (int ks = 0; ks < 2; ks++) {
                int kb = kc*16 + ks*8;    // sL column
                int sb = ks*8;            // Bc row
                int rb = wy4*16 + lg;
                unsigned af[4];
                af[0] = f2tf(sL[(size_t) rb   *SLD + kb+lt]);
                af[1] = f2tf(sL[(size_t)(rb+8)*SLD + kb+lt]);
                af[2] = f2tf(sL[(size_t) rb   *SLD + kb+4+lt]);
                af[3] = f2tf(sL[(size_t)(rb+8)*SLD + kb+4+lt]);
                unsigned bf[4][2];
                #pragma unroll
                for (int fn = 0; fn < 4; fn++) {
                    int cb = wx4*32 + fn*8 + lg;
                    bf[fn][0] = Bc[sb+lt  ][cb];
                    bf[fn][1] = Bc[sb+4+lt][cb];
                }
                #pragma unroll
                for (int fn = 0; fn < 4; fn++)
                    MMA_TF32(acc2[fn], af, bf[fn]);
            }
            if (kc < 31) {
                unsigned (*Bnx)[136] = sB + (1-cur)*16;
                uint4 t;
                t.x = f2tf(rvv.x); t.y = f2tf(rvv.y); t.z = f2tf(rvv.z); t.w = f2tf(rvv.w);
                *(uint4*)(&Bnx[vkk][vdq*4]) = t;
            }
            __syncthreads();
        }
        #pragma unroll
        for (int fn = 0; fn < 4; fn++) {
            #pragma unroll
            for (int q4 = 0; q4 < 4; q4++) {
                int r = wy4*16 + lg + ((q4>=2) ? 8 : 0);
                int c = wx4*32 + fn*8 + lt*2 + (q4&1);
                av[((size_t)b*Sn + m0 + r)*DHn + h*HDn + c] = acc2[fn][q4];
            }
        }
    }
}

// =================== generic linear: C = A@B + bias (EPI1 = GELU) ===================
template<int EPI>
__global__ void __launch_bounds__(256,2) lin_k(
    const float* __restrict__ A, int lda,
    const float* __restrict__ Bw, int ldb,
    const float* __restrict__ bias,
    float* __restrict__ C, int ldc, int coff, int K)
{
    __shared__ unsigned As[2*128][PADA];
    __shared__ unsigned Bs[2*16][136];

    const int m0 = blockIdx.y*128, n0 = blockIdx.x*128;
    const float* Ap = A + (size_t)m0*lda;
    const float* Bp = Bw + n0;

    float acc[4][4][4];
    #pragma unroll
    for (int i=0;i<4;i++) for (int j=0;j<4;j++) for (int r=0;r<4;r++) acc[i][j][r]=0.f;

    gemm_core_db(Ap, lda, Bp, ldb, K, As, Bs, acc);

    const int lane = threadIdx.x & 31, warp = threadIdx.x >> 5;
    const int wy = warp >> 2, wx = warp & 3;
    const int lg = lane >> 2, lt = lane & 3;

    #pragma unroll
    for (int fm=0; fm<4; fm++){
        #pragma unroll
        for (int fn=0; fn<4; fn++){
            int r = wy*64 + fm*16 + lg;
            int c = wx*32 + fn*8 + lt*2;
            #pragma unroll
            for (int q=0; q<4; q++){
                int m = m0 + r + (q>=2 ? 8 : 0);
                int n = n0 + c + (q&1);
                float v = acc[fm][fn][q] + bias[n];
                if (EPI == 1) v = gelu_f(v);
                C[(size_t)m*ldc + coff + n] = v;
            }
        }
    }
}

// ---------------- fused add + LayerNorm ----------------
__global__ void __launch_bounds__(256) add_ln_k(
    const float* __restrict__ a, const float* __restrict__ r,
    const float* __restrict__ g, const float* __restrict__ be,
    float* __restrict__ out)
{
    __shared__ float red[8];
    const int row = blockIdx.x;
    const int t = threadIdx.x;
    const float* ar = a + (size_t)row*Dn;
    const float* rr = r + (size_t)row*Dn;

    float vals[4];
    float s = 0.f;
    #pragma unroll
    for (int c=0;c<4;c++){
        float x = ar[t + c*256] + rr[t + c*256];
        vals[c] = x; s += x;
    }
    #pragma unroll
    for (int o=16;o>0;o>>=1) s += __shfl_xor_sync(0xffffffffu, s, o);
    if ((t & 31) == 0) red[t>>5] = s;
    __syncthreads();
    float tot = 0.f;
    #pragma unroll
    for (int w=0;w<8;w++) tot += red[w];
    float mean = tot * (1.f/1024.f);
    __syncthreads();

    float sq = 0.f;
    #pragma unroll
    for (int c=0;c<4;c++){ float dx = vals[c]-mean; sq += dx*dx; }
    #pragma unroll
    for (int o=16;o>0;o>>=1) sq += __shfl_xor_sync(0xffffffffu, sq, o);
    if ((t & 31) == 0) red[t>>5] = sq;
    __syncthreads();
    float vtot = 0.f;
    #pragma unroll
    for (int w=0;w<8;w++) vtot += red[w];
    float invstd = rsqrtf(vtot*(1.f/1024.f) + 1e-5f);

    #pragma unroll
    for (int c=0;c<4;c++){
        int dd = t + c*256;
        out[(size_t)row*Dn + dd] = (vals[c]-mean)*invstd*g[dd] + be[dd];
    }
}

// ---------------- launch ----------------
#define FATTN_SMEM (64*SLD*4 + 64*68*4 + 2*16*136*4)

extern "C" void kernel_launch(void* const* d_in, const int* in_sizes, int n_in,
                              void* d_out, int out_size)
{
    const float* x      = (const float*)d_in[0];
    const float* mask   = (const float*)d_in[2];
    const float* adjoin = (const float*)d_in[3];
    const float* dist   = (const float*)d_in[4];
    const float* wq1=(const float*)d_in[5],  *bq1=(const float*)d_in[6];
    const float* wk1=(const float*)d_in[7],  *bk1=(const float*)d_in[8];
    const float* wv1=(const float*)d_in[9],  *bv1=(const float*)d_in[10];
    const float* wo1=(const float*)d_in[11], *bo1=(const float*)d_in[12];
    const float* wq2=(const float*)d_in[13], *bq2=(const float*)d_in[14];
    const float* wk2=(const float*)d_in[15], *bk2=(const float*)d_in[16];
    const float* wv2=(const float*)d_in[17], *bv2=(const float*)d_in[18];
    const float* wo2=(const float*)d_in[19], *bo2=(const float*)d_in[20];
    const float* wff1=(const float*)d_in[21], *bff1=(const float*)d_in[22];
    const float* wff2=(const float*)d_in[23], *bff2=(const float*)d_in[24];
    const float* ln1g=(const float*)d_in[25], *ln1b=(const float*)d_in[26];
    const float* ln2g=(const float*)d_in[27], *ln2b=(const float*)d_in[28];

    float* out2 = (float*)d_out;                         // (B,S,D)
    float* aw_l = out2 + (size_t)BSn*Dn;                 // (B,H,S,S)
    float* aw_g = aw_l + (size_t)Bn*Hn*Sn*Sn;            // (B,H,S,S)

    float *q1,*k1,*v1,*q2,*k2,*v2,*av1,*av2,*attn,*out1,*hid,*ffn;
    cudaGetSymbolAddress((void**)&q1, g_q1);
    cudaGetSymbolAddress((void**)&k1, g_k1);
    cudaGetSymbolAddress((void**)&v1, g_v1);
    cudaGetSymbolAddress((void**)&q2, g_q2);
    cudaGetSymbolAddress((void**)&k2, g_k2);
    cudaGetSymbolAddress((void**)&v2, g_v2);
    cudaGetSymbolAddress((void**)&av1, g_av1);
    cudaGetSymbolAddress((void**)&av2, g_av2);
    cudaGetSymbolAddress((void**)&attn, g_attn);
    cudaGetSymbolAddress((void**)&out1, g_out1);
    cudaGetSymbolAddress((void**)&hid, g_hid);
    cudaGetSymbolAddress((void**)&ffn, g_ffn);

    static int smem_set = 0;
    if (!smem_set) {
        cudaFuncSetAttribute(fattn_k, cudaFuncAttributeMaxDynamicSharedMemorySize, FATTN_SMEM);
        smem_set = 1;
    }

    // QKV: 6 fused batched GEMMs (K stored transposed)
    dim3 gqkv(4, 64, 6);
    qkv_k<<<gqkv,256>>>(x, wq1,wk1,wv1,wq2,wk2,wv2,
                           bq1,bk1,bv1,bq2,bk2,bv2,
                           q1,k1,v1,q2,k2,v2);

    // fused attention: score + softmax + aw + AV
    dim3 gfa(8, 256);
    fattn_k<<<gfa,256,FATTN_SMEM>>>(q1,k1,v1, q2,k2,v2,
                                    mask, adjoin, dist,
                                    aw_l, aw_g, av1, av2);

    // output projections -> concat into g_attn (B,S,1024)
    dim3 gop(4, 64);
    lin_k<0><<<gop,256>>>(av1, DHn, wo1, DHn, bo1, attn, Dn, 0,   DHn);
    lin_k<0><<<gop,256>>>(av2, DHn, wo2, DHn, bo2, attn, Dn, DHn, DHn);

    // LN1(x + attn)
    add_ln_k<<<BSn,256>>>(x, attn, ln1g, ln1b, out1);

    // FFN
    dim3 gff1(32, 64);
    lin_k<1><<<gff1,256>>>(out1, Dn, wff1, DFFn, bff1, hid, DFFn, 0, Dn);
    dim3 gff2(8, 64);
    lin_k<0><<<gff2,256>>>(hid, DFFn, wff2, Dn, bff2, ffn, Dn, 0, DFFn);

    // LN2(out1 + ffn) -> out2
    add_ln_k<<<BSn,256>>>(out1, ffn, ln2g, ln2b, out2);
}

// round 10
// speedup vs baseline: 1.0172x; 1.0172x over previous
#include <cuda_runtime.h>
#include <math.h>
#include <stdint.h>

#define Bn   16
#define Sn   512
#define Dn   1024
#define Hn   8
#define DHn  512
#define HDn  64
#define DFFn 4096
#define BSn  (Bn*Sn)   // 8192

// ---------------- scratch (static device globals; no allocation) ----------------
__device__ float g_q1[Bn*Hn*Sn*HDn];
__device__ float g_k1[Bn*Hn*Sn*HDn];   // stored transposed: (B,H,64,S)
__device__ float g_v1[Bn*Hn*Sn*HDn];
__device__ float g_q2[Bn*Hn*Sn*HDn];
__device__ float g_k2[Bn*Hn*Sn*HDn];   // transposed
__device__ float g_v2[Bn*Hn*Sn*HDn];
__device__ float g_av1[BSn*DHn];       // written tf32-rounded
__device__ float g_av2[BSn*DHn];       // written tf32-rounded
__device__ float g_attn[BSn*Dn];
__device__ float g_out1[BSn*Dn];
__device__ float g_out1r[BSn*Dn];      // tf32-rounded copy
__device__ float g_hid[(size_t)BSn*DFFn];   // written tf32-rounded
__device__ float g_ffn[BSn*Dn];
__device__ float g_xr[BSn*Dn];         // tf32-rounded x
// transposed+rounded weights: 8 x 512x512, then ff1t [4096][1024], ff2t [1024][4096]
#define WT_FF1 2097152
#define WT_FF2 (2097152 + 4194304)
__device__ float g_wt[WT_FF2 + 4194304];

__device__ __forceinline__ float gelu_f(float x){
    return 0.5f * x * (1.0f + erff(x * 0.70710678118654752440f));
}
__device__ __forceinline__ unsigned f2tf(float x){
    unsigned u; asm("cvt.rna.tf32.f32 %0, %1;" : "=r"(u) : "f"(x)); return u;
}
__device__ __forceinline__ float roundtf(float x){ return __uint_as_float(f2tf(x)); }

__device__ __forceinline__ uint32_t smem_u32(const void* p){
    uint32_t a;
    asm("{ .reg .u64 t; cvta.to.shared.u64 t, %1; cvt.u32.u64 %0, t; }" : "=r"(a) : "l"(p));
    return a;
}

#define MMA_TF32(acc, af, bf) \
    asm volatile( \
        "mma.sync.aligned.m16n8k8.row.col.f32.tf32.tf32.f32 " \
        "{%0,%1,%2,%3}, {%4,%5,%6,%7}, {%8,%9}, {%0,%1,%2,%3};" \
        : "+f"((acc)[0]), "+f"((acc)[1]), "+f"((acc)[2]), "+f"((acc)[3]) \
        : "r"((af)[0]), "r"((af)[1]), "r"((af)[2]), "r"((af)[3]), \
          "r"((bf)[0]), "r"((bf)[1]))

#define CP16(d, s) asm volatile("cp.async.cg.shared.global [%0], [%1], 16;" :: "r"(d), "l"(s))
#define CPCOMMIT() asm volatile("cp.async.commit_group;" ::: "memory")
#define CPWAIT2()  asm volatile("cp.async.wait_group 2;" ::: "memory")
#define LDSM4(r, a) \
    asm volatile("ldmatrix.sync.aligned.m8n8.x4.shared.b16 {%0,%1,%2,%3}, [%4];" \
        : "=r"((r)[0]), "=r"((r)[1]), "=r"((r)[2]), "=r"((r)[3]) : "r"(a))

// =================== cp.async + ldmatrix pipelined TF32 GEMM core ===================
// 128x128 tile, K slabs of 16, 4 stages. A [M][K] row-major (pre-rounded),
// Bt [N][K] row-major (pre-rounded, = W^T). smem rows padded to 80B (20 floats).
#define NS   4
#define STGA 10240          // 128 rows * 80B
#define STG  (2*STGA)
#define G2_SMEM (NS*STG)    // 81920

__device__ __forceinline__ void core_pipe(
    const float* __restrict__ A, int lda,
    const float* __restrict__ Bt, int ldbt,
    int K, char* smc, float (&acc)[4][4][4])
{
    const int tid = threadIdx.x, lane = tid & 31, warp = tid >> 5;
    const int wy = warp >> 2, wx = warp & 3;
    const uint32_t sb = smem_u32(smc);
    const int lrow = lane & 15;
    const int lc16 = (lane >> 4) & 1;
    const int crow = tid >> 2, ccol = tid & 3;

    const int nslab = K >> 4;
    #pragma unroll
    for (int s = 0; s < NS-1; s++){
        if (s < nslab){
            const int k0 = s << 4;
            uint32_t stA = sb + s*STG;
            uint32_t stB = stA + STGA;
            #pragma unroll
            for (int it = 0; it < 2; it++){
                int r = crow + it*64;
                CP16(stA + r*80 + ccol*16, A  + (size_t)r*lda  + k0 + ccol*4);
                CP16(stB + r*80 + ccol*16, Bt + (size_t)r*ldbt + k0 + ccol*4);
            }
        }
        CPCOMMIT();
    }

    for (int s = 0; s < nslab; s++){
        CPWAIT2();
        __syncthreads();
        {   // issue stage s+NS-1 (overwrites stage s-1, safe past the barrier)
            int nx = s + NS-1;
            if (nx < nslab){
                const int k0 = nx << 4;
                uint32_t stA = sb + (nx & (NS-1))*STG;
                uint32_t stB = stA + STGA;
                #pragma unroll
                for (int it = 0; it < 2; it++){
                    int r = crow + it*64;
                    CP16(stA + r*80 + ccol*16, A  + (size_t)r*lda  + k0 + ccol*4);
                    CP16(stB + r*80 + ccol*16, Bt + (size_t)r*ldbt + k0 + ccol*4);
                }
            }
            CPCOMMIT();
        }
        // compute stage s
        uint32_t aA = sb + (s & (NS-1))*STG;
        uint32_t aB = aA + STGA;
        #pragma unroll
        for (int ks = 0; ks < 2; ks++){
            unsigned af[4][4], bq[2][4];
            #pragma unroll
            for (int fm = 0; fm < 4; fm++){
                uint32_t ad = aA + (uint32_t)((wy*64 + fm*16 + lrow)*80 + ks*32 + lc16*16);
                LDSM4(af[fm], ad);
            }
            #pragma unroll
            for (int p = 0; p < 2; p++){
                uint32_t ad = aB + (uint32_t)((wx*32 + p*16 + lrow)*80 + ks*32 + lc16*16);
                LDSM4(bq[p], ad);
            }
            #pragma unroll
            for (int fm = 0; fm < 4; fm++){
                #pragma unroll
                for (int p = 0; p < 2; p++){
                    unsigned b0[2] = { bq[p][0], bq[p][2] };
                    unsigned b1[2] = { bq[p][1], bq[p][3] };
                    MMA_TF32(acc[fm][2*p],   af[fm], b0);
                    MMA_TF32(acc[fm][2*p+1], af[fm], b1);
                }
            }
        }
    }
}

// =================== prep: round / transpose+round ===================
__global__ void round_k(const float* __restrict__ s, float* __restrict__ d, int n){
    int i = blockIdx.x*blockDim.x + threadIdx.x;
    int st = gridDim.x*blockDim.x;
    for (; i < n; i += st) d[i] = roundtf(s[i]);
}

// transpose src[R][C] -> dst[C][R], rounding at write
__global__ void trp_k(const float* __restrict__ src, float* __restrict__ dst, int R, int C){
    __shared__ float t[32][33];
    int cx = blockIdx.x*32, cy = blockIdx.y*32;
    int tx = threadIdx.x, ty = threadIdx.y;
    #pragma unroll
    for (int i = 0; i < 4; i++)
        t[ty + i*8][tx] = src[(size_t)(cy + ty + i*8)*C + cx + tx];
    __syncthreads();
    #pragma unroll
    for (int i = 0; i < 4; i++)
        dst[(size_t)(cx + ty + i*8)*R + cy + tx] = roundtf(t[tx][ty + i*8]);
}

__global__ void trp8_k(const float* w0, const float* w1, const float* w2, const float* w3,
                       const float* w4, const float* w5, const float* w6, const float* w7,
                       float* __restrict__ dst)
{
    __shared__ float t[32][33];
    const float* src;
    switch (blockIdx.z){
        case 0: src=w0; break; case 1: src=w1; break; case 2: src=w2; break; case 3: src=w3; break;
        case 4: src=w4; break; case 5: src=w5; break; case 6: src=w6; break; default: src=w7; break;
    }
    float* d = dst + (size_t)blockIdx.z*262144;
    int cx = blockIdx.x*32, cy = blockIdx.y*32;
    int tx = threadIdx.x, ty = threadIdx.y;
    #pragma unroll
    for (int i = 0; i < 4; i++)
        t[ty + i*8][tx] = src[(size_t)(cy + ty + i*8)*512 + cx + tx];
    __syncthreads();
    #pragma unroll
    for (int i = 0; i < 4; i++)
        d[(size_t)(cx + ty + i*8)*512 + cy + tx] = roundtf(t[tx][ty + i*8]);
}

// =================== QKV: 6 batched GEMMs, scatter epilogue ===================
__global__ void __launch_bounds__(256,2) qkv_k(
    const float* __restrict__ xr, const float* __restrict__ wt,
    const float* b0, const float* b1, const float* b2,
    const float* b3, const float* b4, const float* b5,
    float* o0, float* o1, float* o2, float* o3, float* o4, float* o5)
{
    extern __shared__ char smc[];
    const int z = blockIdx.z;
    const float* bi; float* dst;
    switch (z) {
        case 0: bi=b0; dst=o0; break;
        case 1: bi=b1; dst=o1; break;
        case 2: bi=b2; dst=o2; break;
        case 3: bi=b3; dst=o3; break;
        case 4: bi=b4; dst=o4; break;
        default:bi=b5; dst=o5; break;
    }
    const int m0 = blockIdx.y*128, n0 = blockIdx.x*128;
    const float* A  = xr + (z>=3 ? DHn : 0) + (size_t)m0*Dn;
    const float* Bt = wt + (size_t)z*262144 + (size_t)n0*DHn;

    float acc[4][4][4];
    #pragma unroll
    for (int i=0;i<4;i++) for (int j=0;j<4;j++) for (int r=0;r<4;r++) acc[i][j][r]=0.f;

    core_pipe(A, Dn, Bt, DHn, DHn, smc, acc);

    const int lane = threadIdx.x & 31, warp = threadIdx.x >> 5;
    const int wy = warp >> 2, wx = warp & 3;
    const int lg = lane >> 2, lt = lane & 3;
    const bool isK = (z==1 || z==4);

    #pragma unroll
    for (int fm=0; fm<4; fm++){
        #pragma unroll
        for (int fn=0; fn<4; fn++){
            int r = wy*64 + fm*16 + lg;
            int c = wx*32 + fn*8 + lt*2;
            #pragma unroll
            for (int q=0; q<4; q++){
                int m = m0 + r + (q>=2 ? 8 : 0);
                int n = n0 + c + (q&1);
                float v = acc[fm][fn][q] + bi[n];
                int b = m>>9, s = m&511, h = n>>6, d = n&63;
                if (isK) dst[(((size_t)(b*8+h))*64 + d)*512 + s] = v;
                else     dst[(((size_t)(b*8+h))*512 + s)*64 + d] = v;
            }
        }
    }
}

// =================== generic linear (pipelined): C = A@W + bias ===================
// EPI 0: plain;  EPI 1: GELU + tf32-round (for hid)
template<int EPI>
__global__ void __launch_bounds__(256,2) lin_k(
    const float* __restrict__ A, int lda,
    const float* __restrict__ Bt, int K,
    const float* __restrict__ bias,
    float* __restrict__ C, int ldc, int coff)
{
    extern __shared__ char smc[];
    const int m0 = blockIdx.y*128, n0 = blockIdx.x*128;
    const float* Ap  = A  + (size_t)m0*lda;
    const float* Btp = Bt + (size_t)n0*K;

    float acc[4][4][4];
    #pragma unroll
    for (int i=0;i<4;i++) for (int j=0;j<4;j++) for (int r=0;r<4;r++) acc[i][j][r]=0.f;

    core_pipe(Ap, lda, Btp, K, K, smc, acc);

    const int lane = threadIdx.x & 31, warp = threadIdx.x >> 5;
    const int wy = warp >> 2, wx = warp & 3;
    const int lg = lane >> 2, lt = lane & 3;

    #pragma unroll
    for (int fm=0; fm<4; fm++){
        #pragma unroll
        for (int fn=0; fn<4; fn++){
            int r = wy*64 + fm*16 + lg;
            int c = wx*32 + fn*8 + lt*2;
            #pragma unroll
            for (int q=0; q<4; q++){
                int m = m0 + r + (q>=2 ? 8 : 0);
                int n = n0 + c + (q&1);
                float v = acc[fm][fn][q] + bias[n];
                if (EPI == 1) v = roundtf(gelu_f(v));
                C[(size_t)m*ldc + coff + n] = v;
            }
        }
    }
}

// =================== fused attention: score + softmax + aw write + AV ===================
#define SLD 516
#define PADA 20

__global__ void __launch_bounds__(256,1) fattn_k(
    const float* __restrict__ q1, const float* __restrict__ k1, const float* __restrict__ v1,
    const float* __restrict__ q2, const float* __restrict__ k2, const float* __restrict__ v2,
    const float* __restrict__ mask, const float* __restrict__ adjoin, const float* __restrict__ dist,
    float* __restrict__ aw_l, float* __restrict__ aw_g,
    float* __restrict__ av1, float* __restrict__ av2)
{
    extern __shared__ char smem_raw[];
    float* sL = (float*)smem_raw;                                        // [64][SLD]
    unsigned (*sQ)[68]  = (unsigned(*)[68]) (smem_raw + 64*SLD*4);       // [64][68]
    unsigned (*sB)[136] = (unsigned(*)[136])(smem_raw + 64*SLD*4 + 64*68*4); // [2*16][136]

    const int tid = threadIdx.x, lane = tid & 31, warp = tid >> 5;
    const int lg = lane >> 2, lt = lane & 3;
    const int zi = blockIdx.y;
    const int sel = zi >> 7, zb = zi & 127;
    const int b = zb >> 3, h = zb & 7;
    const int m0 = blockIdx.x * 64;

    const float* q  = (sel ? q2 : q1) + (size_t)zb*Sn*HDn;
    const float* kT = (sel ? k2 : k1) + (size_t)zb*HDn*Sn;
    const float* v  = (sel ? v2 : v1) + (size_t)zb*Sn*HDn;
    float* aw = (sel ? aw_g : aw_l) + (size_t)zb*Sn*Sn;
    float* av = sel ? av2 : av1;
    const float* extra = (sel ? dist : adjoin) + (size_t)b*Sn*Sn;
    const float* mrow  = mask + (size_t)b*Sn;

    #pragma unroll
    for (int it = 0; it < 4; it++) {
        int l = tid + it*256;
        int row = l >> 4, dq = l & 15;
        float4 a = *(const float4*)(q + (size_t)(m0+row)*HDn + dq*4);
        uint4 t;
        t.x = f2tf(a.x); t.y = f2tf(a.y); t.z = f2tf(a.z); t.w = f2tf(a.w);
        *(uint4*)(&sQ[row][dq*4]) = t;
    }

    {
        const int wy = warp >> 2, wx = warp & 3;
        const int bkk = tid >> 5, bnq = tid & 31;
        for (int n0b = 0; n0b < 512; n0b += 128) {
            float acc[2][4][4];
            #pragma unroll
            for (int i=0;i<2;i++) for (int j=0;j<4;j++) for (int r=0;r<4;r++) acc[i][j][r]=0.f;

            float4 rk[2];
            #pragma unroll
            for (int it = 0; it < 2; it++)
                rk[it] = *(const float4*)(kT + (size_t)(bkk + it*8)*Sn + n0b + bnq*4);
            #pragma unroll
            for (int it = 0; it < 2; it++) {
                uint4 t;
                t.x = f2tf(rk[it].x); t.y = f2tf(rk[it].y);
                t.z = f2tf(rk[it].z); t.w = f2tf(rk[it].w);
                *(uint4*)(&sB[bkk + it*8][bnq*4]) = t;
            }
            __syncthreads();

            for (int kc = 0; kc < 4; kc++) {
                const int cur = kc & 1;
                if (kc < 3) {
                    #pragma unroll
                    for (int it = 0; it < 2; it++)
                        rk[it] = *(const float4*)(kT + (size_t)(kc*16 + 16 + bkk + it*8)*Sn + n0b + bnq*4);
                }
                unsigned (*Bc)[136] = sB + cur*16;
                #pragma unroll
                for (int ks = 0; ks < 2; ks++) {
                    int kb = kc*16 + ks*8;
                    int sbm = ks*8;
                    unsigned af[2][4], bf[4][2];
                    #pragma unroll
                    for (int fm = 0; fm < 2; fm++) {
                        int rb = wy*32 + fm*16 + lg;
                        af[fm][0] = sQ[rb  ][kb+lt];
                        af[fm][1] = sQ[rb+8][kb+lt];
                        af[fm][2] = sQ[rb  ][kb+4+lt];
                        af[fm][3] = sQ[rb+8][kb+4+lt];
                    }
                    #pragma unroll
                    for (int fn = 0; fn < 4; fn++) {
                        int cb = wx*32 + fn*8 + lg;
                        bf[fn][0] = Bc[sbm+lt  ][cb];
                        bf[fn][1] = Bc[sbm+4+lt][cb];
                    }
                    #pragma unroll
                    for (int fm = 0; fm < 2; fm++)
                        #pragma unroll
                        for (int fn = 0; fn < 4; fn++)
                            MMA_TF32(acc[fm][fn], af[fm], bf[fn]);
                }
                if (kc < 3) {
                    unsigned (*Bnx)[136] = sB + (1-cur)*16;
                    #pragma unroll
                    for (int it = 0; it < 2; it++) {
                        uint4 t;
                        t.x = f2tf(rk[it].x); t.y = f2tf(rk[it].y);
                        t.z = f2tf(rk[it].z); t.w = f2tf(rk[it].w);
                        *(uint4*)(&Bnx[bkk + it*8][bnq*4]) = t;
                    }
                }
                __syncthreads();
            }
            #pragma unroll
            for (int fm = 0; fm < 2; fm++) {
                #pragma unroll
                for (int fn = 0; fn < 4; fn++) {
                    #pragma unroll
                    for (int q4 = 0; q4 < 4; q4++) {
                        int r = wy*32 + fm*16 + lg + ((q4>=2) ? 8 : 0);
                        int c = wx*32 + fn*8 + lt*2 + (q4&1);
                        int j = n0b + c;
                        float s = acc[fm][fn][q4];
                        float logit;
                        if (sel == 0) {
                            logit = s*0.125f + mrow[j]*(-1.0e9f)
                                  + extra[(size_t)(m0+r)*Sn + j];
                        } else {
                            float w  = extra[(size_t)(m0+r)*Sn + j];
                            float rs = 3.7182818284590452f / (1.f + expf(1.f - w));
                            logit = fmaxf(s, 0.f)*rs*0.125f + mrow[j]*(-1.0e9f);
                        }
                        sL[r*SLD + j] = logit;
                    }
                }
            }
        }
    }
    __syncthreads();

    for (int rr = 0; rr < 8; rr++) {
        int r = warp*8 + rr;
        float4* rowp = (float4*)(sL + (size_t)r*SLD);
        float4 rv[4];
        float lmax = -3.0e38f;
        #pragma unroll
        for (int it = 0; it < 4; it++) {
            float4 v4 = rowp[it*32 + lane];
            rv[it] = v4;
            lmax = fmaxf(lmax, fmaxf(fmaxf(v4.x, v4.y), fmaxf(v4.z, v4.w)));
        }
        #pragma unroll
        for (int o = 16; o > 0; o >>= 1)
            lmax = fmaxf(lmax, __shfl_xor_sync(0xffffffffu, lmax, o));
        float sum = 0.f;
        #pragma unroll
        for (int it = 0; it < 4; it++) {
            rv[it].x = expf(rv[it].x - lmax);
            rv[it].y = expf(rv[it].y - lmax);
            rv[it].z = expf(rv[it].z - lmax);
            rv[it].w = expf(rv[it].w - lmax);
            sum += rv[it].x + rv[it].y + rv[it].z + rv[it].w;
        }
        #pragma unroll
        for (int o = 16; o > 0; o >>= 1)
            sum += __shfl_xor_sync(0xffffffffu, sum, o);
        float inv = 1.f / sum;
        float4* awp = (float4*)(aw + (size_t)(m0+r)*Sn);
        #pragma unroll
        for (int it = 0; it < 4; it++) {
            rv[it].x *= inv; rv[it].y *= inv; rv[it].z *= inv; rv[it].w *= inv;
            rowp[it*32 + lane] = rv[it];
            awp[it*32 + lane]  = rv[it];
        }
    }
    __syncthreads();

    {
        const int wy4 = warp >> 1, wx4 = warp & 1;
        const int vkk = tid >> 4, vdq = tid & 15;
        float acc2[4][4];
        #pragma unroll
        for (int j=0;j<4;j++) for (int r=0;r<4;r++) acc2[j][r]=0.f;

        float4 rvv;
        rvv = *(const float4*)(v + (size_t)vkk*HDn + vdq*4);
        {
            uint4 t;
            t.x = f2tf(rvv.x); t.y = f2tf(rvv.y); t.z = f2tf(rvv.z); t.w = f2tf(rvv.w);
            *(uint4*)(&sB[vkk][vdq*4]) = t;
        }
        __syncthreads();

        for (int kc = 0; kc < 32; kc++) {
            const int cur = kc & 1;
            if (kc < 31)
                rvv = *(const float4*)(v + (size_t)(kc*16 + 16 + vkk)*HDn + vdq*4);

            unsigned (*Bc)[136] = sB + cur*16;
            #pragma unroll
            for (int ks = 0; ks < 2; ks++) {
                int kb = kc*16 + ks*8;
                int sbm = ks*8;
                int rb = wy4*16 + lg;
                unsigned af[4];
                af[0] = f2tf(sL[(size_t) rb   *SLD + kb+lt]);
                af[1] = f2tf(sL[(size_t)(rb+8)*SLD + kb+lt]);
                af[2] = f2tf(sL[(size_t) rb   *SLD + kb+4+lt]);
                af[3] = f2tf(sL[(size_t)(rb+8)*SLD + kb+4+lt]);
                unsigned bf[4][2];
                #pragma unroll
                for (int fn = 0; fn < 4; fn++) {
                    int cb = wx4*32 + fn*8 + lg;
                    bf[fn][0] = Bc[sbm+lt  ][cb];
                    bf[fn][1] = Bc[sbm+4+lt][cb];
                }
                #pragma unroll
                for (int fn = 0; fn < 4; fn++)
                    MMA_TF32(acc2[fn], af, bf[fn]);
            }
            if (kc < 31) {
                unsigned (*Bnx)[136] = sB + (1-cur)*16;
                uint4 t;
                t.x = f2tf(rvv.x); t.y = f2tf(rvv.y); t.z = f2tf(rvv.z); t.w = f2tf(rvv.w);
                *(uint4*)(&Bnx[vkk][vdq*4]) = t;
            }
            __syncthreads();
        }
        #pragma unroll
        for (int fn = 0; fn < 4; fn++) {
            #pragma unroll
            for (int q4 = 0; q4 < 4; q4++) {
                int r = wy4*16 + lg + ((q4>=2) ? 8 : 0);
                int c = wx4*32 + fn*8 + lt*2 + (q4&1);
                // rounded: out-proj consumes this as tf32 anyway (bit-identical)
                av[((size_t)b*Sn + m0 + r)*DHn + h*HDn + c] = roundtf(acc2[fn][q4]);
            }
        }
    }
}

// ---------------- fused add + LayerNorm (optional rounded copy) ----------------
__global__ void __launch_bounds__(256) add_ln_k(
    const float* __restrict__ a, const float* __restrict__ r,
    const float* __restrict__ g, const float* __restrict__ be,
    float* __restrict__ out, float* __restrict__ outr)
{
    __shared__ float red[8];
    const int row = blockIdx.x;
    const int t = threadIdx.x;
    const float* ar = a + (size_t)row*Dn;
    const float* rr = r + (size_t)row*Dn;

    float vals[4];
    float s = 0.f;
    #pragma unroll
    for (int c=0;c<4;c++){
        float x = ar[t + c*256] + rr[t + c*256];
        vals[c] = x; s += x;
    }
    #pragma unroll
    for (int o=16;o>0;o>>=1) s += __shfl_xor_sync(0xffffffffu, s, o);
    if ((t & 31) == 0) red[t>>5] = s;
    __syncthreads();
    float tot = 0.f;
    #pragma unroll
    for (int w=0;w<8;w++) tot += red[w];
    float mean = tot * (1.f/1024.f);
    __syncthreads();

    float sq = 0.f;
    #pragma unroll
    for (int c=0;c<4;c++){ float dx = vals[c]-mean; sq += dx*dx; }
    #pragma unroll
    for (int o=16;o>0;o>>=1) sq += __shfl_xor_sync(0xffffffffu, sq, o);
    if ((t & 31) == 0) red[t>>5] = sq;
    __syncthreads();
    float vtot = 0.f;
    #pragma unroll
    for (int w=0;w<8;w++) vtot += red[w];
    float invstd = rsqrtf(vtot*(1.f/1024.f) + 1e-5f);

    #pragma unroll
    for (int c=0;c<4;c++){
        int dd = t + c*256;
        float o = (vals[c]-mean)*invstd*g[dd] + be[dd];
        out[(size_t)row*Dn + dd] = o;
        if (outr) outr[(size_t)row*Dn + dd] = roundtf(o);
    }
}

// ---------------- launch ----------------
#define FATTN_SMEM (64*SLD*4 + 64*68*4 + 2*16*136*4)

extern "C" void kernel_launch(void* const* d_in, const int* in_sizes, int n_in,
                              void* d_out, int out_size)
{
    const float* x      = (const float*)d_in[0];
    const float* mask   = (const float*)d_in[2];
    const float* adjoin = (const float*)d_in[3];
    const float* dist   = (const float*)d_in[4];
    const float* wq1=(const float*)d_in[5],  *bq1=(const float*)d_in[6];
    const float* wk1=(const float*)d_in[7],  *bk1=(const float*)d_in[8];
    const float* wv1=(const float*)d_in[9],  *bv1=(const float*)d_in[10];
    const float* wo1=(const float*)d_in[11], *bo1=(const float*)d_in[12];
    const float* wq2=(const float*)d_in[13], *bq2=(const float*)d_in[14];
    const float* wk2=(const float*)d_in[15], *bk2=(const float*)d_in[16];
    const float* wv2=(const float*)d_in[17], *bv2=(const float*)d_in[18];
    const float* wo2=(const float*)d_in[19], *bo2=(const float*)d_in[20];
    const float* wff1=(const float*)d_in[21], *bff1=(const float*)d_in[22];
    const float* wff2=(const float*)d_in[23], *bff2=(const float*)d_in[24];
    const float* ln1g=(const float*)d_in[25], *ln1b=(const float*)d_in[26];
    const float* ln2g=(const float*)d_in[27], *ln2b=(const float*)d_in[28];

    float* out2 = (float*)d_out;                         // (B,S,D)
    float* aw_l = out2 + (size_t)BSn*Dn;                 // (B,H,S,S)
    float* aw_g = aw_l + (size_t)Bn*Hn*Sn*Sn;            // (B,H,S,S)

    float *q1,*k1,*v1,*q2,*k2,*v2,*av1,*av2,*attn,*out1,*out1r,*hid,*ffn,*xr,*wt;
    cudaGetSymbolAddress((void**)&q1, g_q1);
    cudaGetSymbolAddress((void**)&k1, g_k1);
    cudaGetSymbolAddress((void**)&v1, g_v1);
    cudaGetSymbolAddress((void**)&q2, g_q2);
    cudaGetSymbolAddress((void**)&k2, g_k2);
    cudaGetSymbolAddress((void**)&v2, g_v2);
    cudaGetSymbolAddress((void**)&av1, g_av1);
    cudaGetSymbolAddress((void**)&av2, g_av2);
    cudaGetSymbolAddress((void**)&attn, g_attn);
    cudaGetSymbolAddress((void**)&out1, g_out1);
    cudaGetSymbolAddress((void**)&out1r, g_out1r);
    cudaGetSymbolAddress((void**)&hid, g_hid);
    cudaGetSymbolAddress((void**)&ffn, g_ffn);
    cudaGetSymbolAddress((void**)&xr, g_xr);
    cudaGetSymbolAddress((void**)&wt, g_wt);

    static int smem_set = 0;
    if (!smem_set) {
        cudaFuncSetAttribute(fattn_k, cudaFuncAttributeMaxDynamicSharedMemorySize, FATTN_SMEM);
        cudaFuncSetAttribute(qkv_k,    cudaFuncAttributeMaxDynamicSharedMemorySize, G2_SMEM);
        cudaFuncSetAttribute(lin_k<0>, cudaFuncAttributeMaxDynamicSharedMemorySize, G2_SMEM);
        cudaFuncSetAttribute(lin_k<1>, cudaFuncAttributeMaxDynamicSharedMemorySize, G2_SMEM);
        smem_set = 1;
    }

    // ---- prep: round x; transpose+round all weights ----
    round_k<<<512,256>>>(x, xr, BSn*Dn);
    trp8_k<<<dim3(16,16,8), dim3(32,8)>>>(wq1,wk1,wv1,wq2,wk2,wv2,wo1,wo2, wt);
    trp_k<<<dim3(128,32), dim3(32,8)>>>(wff1, wt + WT_FF1, 1024, 4096);   // -> [4096][1024]
    trp_k<<<dim3(32,128), dim3(32,8)>>>(wff2, wt + WT_FF2, 4096, 1024);   // -> [1024][4096]

    // ---- QKV: 6 fused batched GEMMs (K stored transposed) ----
    dim3 gqkv(4, 64, 6);
    qkv_k<<<gqkv,256,G2_SMEM>>>(xr, wt, bq1,bk1,bv1,bq2,bk2,bv2,
                                q1,k1,v1,q2,k2,v2);

    // ---- fused attention ----
    dim3 gfa(8, 256);
    fattn_k<<<gfa,256,FATTN_SMEM>>>(q1,k1,v1, q2,k2,v2,
                                    mask, adjoin, dist,
                                    aw_l, aw_g, av1, av2);

    // ---- output projections -> concat into g_attn ----
    dim3 gop(4, 64);
    lin_k<0><<<gop,256,G2_SMEM>>>(av1, DHn, wt + 6*262144, DHn, bo1, attn, Dn, 0);
    lin_k<0><<<gop,256,G2_SMEM>>>(av2, DHn, wt + 7*262144, DHn, bo2, attn, Dn, DHn);

    // ---- LN1(x + attn) -> out1 (+ rounded copy) ----
    add_ln_k<<<BSn,256>>>(x, attn, ln1g, ln1b, out1, out1r);

    // ---- FFN ----
    dim3 gff1(32, 64);
    lin_k<1><<<gff1,256,G2_SMEM>>>(out1r, Dn, wt + WT_FF1, Dn, bff1, hid, DFFn, 0);
    dim3 gff2(8, 64);
    lin_k<0><<<gff2,256,G2_SMEM>>>(hid, DFFn, wt + WT_FF2, DFFn, bff2, ffn, Dn, 0);

    // ---- LN2(out1 + ffn) -> out2 ----
    add_ln_k<<<BSn,256>>>(out1, ffn, ln2g, ln2b, out2, (float*)0);
}

// round 11
// speedup vs baseline: 1.3886x; 1.3651x over previous
#include <cuda_runtime.h>
#include <cuda_fp16.h>
#include <math.h>
#include <stdint.h>

#define Bn   16
#define Sn   512
#define Dn   1024
#define Hn   8
#define DHn  512
#define HDn  64
#define DFFn 4096
#define BSn  (Bn*Sn)   // 8192

// ---------------- scratch (static device globals; no allocation) ----------------
__device__ float g_q1[Bn*Hn*Sn*HDn];
__device__ float g_k1[Bn*Hn*Sn*HDn];   // stored transposed: (B,H,64,S)
__device__ float g_v1[Bn*Hn*Sn*HDn];
__device__ float g_q2[Bn*Hn*Sn*HDn];
__device__ float g_k2[Bn*Hn*Sn*HDn];   // transposed
__device__ float g_v2[Bn*Hn*Sn*HDn];
__device__ __half g_av1[BSn*DHn];      // half (fattn epilogue)
__device__ __half g_av2[BSn*DHn];
__device__ float g_attn[BSn*Dn];
__device__ float g_out1[BSn*Dn];
__device__ __half g_out1r[BSn*Dn];     // half copy for FFN1
__device__ __half g_hid[(size_t)BSn*DFFn];  // half (FFN1 epilogue)
__device__ float g_ffn[BSn*Dn];
__device__ __half g_xr[BSn*Dn];        // half x
// transposed+half weights: 8 x 512x512, then ff1t [4096][1024], ff2t [1024][4096]
#define WT_FF1 2097152
#define WT_FF2 (2097152 + 4194304)
__device__ __half g_wt[WT_FF2 + 4194304];

__device__ __forceinline__ float gelu_f(float x){
    return 0.5f * x * (1.0f + erff(x * 0.70710678118654752440f));
}
__device__ __forceinline__ unsigned f2tf(float x){
    unsigned u; asm("cvt.rna.tf32.f32 %0, %1;" : "=r"(u) : "f"(x)); return u;
}

__device__ __forceinline__ uint32_t smem_u32(const void* p){
    uint32_t a;
    asm("{ .reg .u64 t; cvta.to.shared.u64 t, %1; cvt.u32.u64 %0, t; }" : "=r"(a) : "l"(p));
    return a;
}

#define MMA_TF32(acc, af, bf) \
    asm volatile( \
        "mma.sync.aligned.m16n8k8.row.col.f32.tf32.tf32.f32 " \
        "{%0,%1,%2,%3}, {%4,%5,%6,%7}, {%8,%9}, {%0,%1,%2,%3};" \
        : "+f"((acc)[0]), "+f"((acc)[1]), "+f"((acc)[2]), "+f"((acc)[3]) \
        : "r"((af)[0]), "r"((af)[1]), "r"((af)[2]), "r"((af)[3]), \
          "r"((bf)[0]), "r"((bf)[1]))

#define MMA_F16(acc, af, bf) \
    asm volatile( \
        "mma.sync.aligned.m16n8k16.row.col.f32.f16.f16.f32 " \
        "{%0,%1,%2,%3}, {%4,%5,%6,%7}, {%8,%9}, {%0,%1,%2,%3};" \
        : "+f"((acc)[0]), "+f"((acc)[1]), "+f"((acc)[2]), "+f"((acc)[3]) \
        : "r"((af)[0]), "r"((af)[1]), "r"((af)[2]), "r"((af)[3]), \
          "r"((bf)[0]), "r"((bf)[1]))

#define CP16(d, s) asm volatile("cp.async.cg.shared.global [%0], [%1], 16;" :: "r"(d), "l"(s))
#define CPCOMMIT() asm volatile("cp.async.commit_group;" ::: "memory")
#define CPWAIT2()  asm volatile("cp.async.wait_group 2;" ::: "memory")
#define LDSM4(r, a) \
    asm volatile("ldmatrix.sync.aligned.m8n8.x4.shared.b16 {%0,%1,%2,%3}, [%4];" \
        : "=r"((r)[0]), "=r"((r)[1]), "=r"((r)[2]), "=r"((r)[3]) : "r"(a))

// =================== cp.async + ldmatrix pipelined FP16 GEMM core ===================
// 128x128 tile, K slabs of 32 halves (64B rows padded to 80B), 4 stages.
// A [M][K] row-major half, Bt [N][K] row-major half (= W^T).
#define NS   4
#define STGA 10240          // 128 rows * 80B
#define STG  (2*STGA)
#define G2_SMEM (NS*STG)    // 81920

__device__ __forceinline__ void core_pipe_h(
    const __half* __restrict__ A, int lda,
    const __half* __restrict__ Bt, int ldbt,
    int K, char* smc, float (&acc)[4][4][4])
{
    const int tid = threadIdx.x, lane = tid & 31, warp = tid >> 5;
    const int wy = warp >> 2, wx = warp & 3;
    const uint32_t sb = smem_u32(smc);
    const int lrow = lane & 15;
    const int lc16 = (lane >> 4) & 1;
    const int crow = tid >> 2, ccol = tid & 3;   // 4 x 16B chunks per 64B row

    const int nslab = K >> 5;
    #pragma unroll
    for (int s = 0; s < NS-1; s++){
        if (s < nslab){
            const int k0 = s << 5;
            uint32_t stA = sb + s*STG;
            uint32_t stB = stA + STGA;
            #pragma unroll
            for (int it = 0; it < 2; it++){
                int r = crow + it*64;
                CP16(stA + r*80 + ccol*16, A  + (size_t)r*lda  + k0 + ccol*8);
                CP16(stB + r*80 + ccol*16, Bt + (size_t)r*ldbt + k0 + ccol*8);
            }
        }
        CPCOMMIT();
    }

    for (int s = 0; s < nslab; s++){
        CPWAIT2();
        __syncthreads();
        {
            int nx = s + NS-1;
            if (nx < nslab){
                const int k0 = nx << 5;
                uint32_t stA = sb + (nx & (NS-1))*STG;
                uint32_t stB = stA + STGA;
                #pragma unroll
                for (int it = 0; it < 2; it++){
                    int r = crow + it*64;
                    CP16(stA + r*80 + ccol*16, A  + (size_t)r*lda  + k0 + ccol*8);
                    CP16(stB + r*80 + ccol*16, Bt + (size_t)r*ldbt + k0 + ccol*8);
                }
            }
            CPCOMMIT();
        }
        uint32_t aA = sb + (s & (NS-1))*STG;
        uint32_t aB = aA + STGA;
        #pragma unroll
        for (int ks = 0; ks < 2; ks++){          // two k16 halves of the 32-K slab
            unsigned af[4][4], bq[2][4];
            #pragma unroll
            for (int fm = 0; fm < 4; fm++){
                uint32_t ad = aA + (uint32_t)((wy*64 + fm*16 + lrow)*80 + ks*32 + lc16*16);
                LDSM4(af[fm], ad);
            }
            #pragma unroll
            for (int p = 0; p < 2; p++){
                uint32_t ad = aB + (uint32_t)((wx*32 + p*16 + lrow)*80 + ks*32 + lc16*16);
                LDSM4(bq[p], ad);
            }
            #pragma unroll
            for (int fm = 0; fm < 4; fm++){
                #pragma unroll
                for (int p = 0; p < 2; p++){
                    unsigned b0[2] = { bq[p][0], bq[p][2] };
                    unsigned b1[2] = { bq[p][1], bq[p][3] };
                    MMA_F16(acc[fm][2*p],   af[fm], b0);
                    MMA_F16(acc[fm][2*p+1], af[fm], b1);
                }
            }
        }
    }
}

// =================== prep: convert / transpose+convert to half ===================
__global__ void round_k(const float* __restrict__ s, __half* __restrict__ d, int n){
    int i = blockIdx.x*blockDim.x + threadIdx.x;
    int st = gridDim.x*blockDim.x;
    for (; i < n; i += st) d[i] = __float2half(s[i]);
}

// transpose src[R][C] -> dst[C][R], converting at write
__global__ void trp_k(const float* __restrict__ src, __half* __restrict__ dst, int R, int C){
    __shared__ float t[32][33];
    int cx = blockIdx.x*32, cy = blockIdx.y*32;
    int tx = threadIdx.x, ty = threadIdx.y;
    #pragma unroll
    for (int i = 0; i < 4; i++)
        t[ty + i*8][tx] = src[(size_t)(cy + ty + i*8)*C + cx + tx];
    __syncthreads();
    #pragma unroll
    for (int i = 0; i < 4; i++)
        dst[(size_t)(cx + ty + i*8)*R + cy + tx] = __float2half(t[tx][ty + i*8]);
}

__global__ void trp8_k(const float* w0, const float* w1, const float* w2, const float* w3,
                       const float* w4, const float* w5, const float* w6, const float* w7,
                       __half* __restrict__ dst)
{
    __shared__ float t[32][33];
    const float* src;
    switch (blockIdx.z){
        case 0: src=w0; break; case 1: src=w1; break; case 2: src=w2; break; case 3: src=w3; break;
        case 4: src=w4; break; case 5: src=w5; break; case 6: src=w6; break; default: src=w7; break;
    }
    __half* d = dst + (size_t)blockIdx.z*262144;
    int cx = blockIdx.x*32, cy = blockIdx.y*32;
    int tx = threadIdx.x, ty = threadIdx.y;
    #pragma unroll
    for (int i = 0; i < 4; i++)
        t[ty + i*8][tx] = src[(size_t)(cy + ty + i*8)*512 + cx + tx];
    __syncthreads();
    #pragma unroll
    for (int i = 0; i < 4; i++)
        d[(size_t)(cx + ty + i*8)*512 + cy + tx] = __float2half(t[tx][ty + i*8]);
}

// =================== QKV: 6 batched GEMMs, scatter epilogue ===================
__global__ void __launch_bounds__(256,2) qkv_k(
    const __half* __restrict__ xr, const __half* __restrict__ wt,
    const float* b0, const float* b1, const float* b2,
    const float* b3, const float* b4, const float* b5,
    float* o0, float* o1, float* o2, float* o3, float* o4, float* o5)
{
    extern __shared__ char smc[];
    const int z = blockIdx.z;
    const float* bi; float* dst;
    switch (z) {
        case 0: bi=b0; dst=o0; break;
        case 1: bi=b1; dst=o1; break;
        case 2: bi=b2; dst=o2; break;
        case 3: bi=b3; dst=o3; break;
        case 4: bi=b4; dst=o4; break;
        default:bi=b5; dst=o5; break;
    }
    const int m0 = blockIdx.y*128, n0 = blockIdx.x*128;
    const __half* A  = xr + (z>=3 ? DHn : 0) + (size_t)m0*Dn;
    const __half* Bt = wt + (size_t)z*262144 + (size_t)n0*DHn;

    float acc[4][4][4];
    #pragma unroll
    for (int i=0;i<4;i++) for (int j=0;j<4;j++) for (int r=0;r<4;r++) acc[i][j][r]=0.f;

    core_pipe_h(A, Dn, Bt, DHn, DHn, smc, acc);

    const int lane = threadIdx.x & 31, warp = threadIdx.x >> 5;
    const int wy = warp >> 2, wx = warp & 3;
    const int lg = lane >> 2, lt = lane & 3;
    const bool isK = (z==1 || z==4);

    #pragma unroll
    for (int fm=0; fm<4; fm++){
        #pragma unroll
        for (int fn=0; fn<4; fn++){
            int r = wy*64 + fm*16 + lg;
            int c = wx*32 + fn*8 + lt*2;
            #pragma unroll
            for (int q=0; q<4; q++){
                int m = m0 + r + (q>=2 ? 8 : 0);
                int n = n0 + c + (q&1);
                float v = acc[fm][fn][q] + bi[n];
                int b = m>>9, s = m&511, h = n>>6, d = n&63;
                if (isK) dst[(((size_t)(b*8+h))*64 + d)*512 + s] = v;
                else     dst[(((size_t)(b*8+h))*512 + s)*64 + d] = v;
            }
        }
    }
}

// =================== generic linear (pipelined): C = A@W + bias ===================
// EPI 0: fp32 out;  EPI 1: GELU -> half out (hid)
template<int EPI>
__global__ void __launch_bounds__(256,2) lin_k(
    const __half* __restrict__ A, int lda,
    const __half* __restrict__ Bt, int K,
    const float* __restrict__ bias,
    float* __restrict__ C, __half* __restrict__ Ch, int ldc, int coff)
{
    extern __shared__ char smc[];
    const int m0 = blockIdx.y*128, n0 = blockIdx.x*128;
    const __half* Ap  = A  + (size_t)m0*lda;
    const __half* Btp = Bt + (size_t)n0*K;

    float acc[4][4][4];
    #pragma unroll
    for (int i=0;i<4;i++) for (int j=0;j<4;j++) for (int r=0;r<4;r++) acc[i][j][r]=0.f;

    core_pipe_h(Ap, lda, Btp, K, K, smc, acc);

    const int lane = threadIdx.x & 31, warp = threadIdx.x >> 5;
    const int wy = warp >> 2, wx = warp & 3;
    const int lg = lane >> 2, lt = lane & 3;

    #pragma unroll
    for (int fm=0; fm<4; fm++){
        #pragma unroll
        for (int fn=0; fn<4; fn++){
            int r = wy*64 + fm*16 + lg;
            int c = wx*32 + fn*8 + lt*2;
            #pragma unroll
            for (int q=0; q<4; q++){
                int m = m0 + r + (q>=2 ? 8 : 0);
                int n = n0 + c + (q&1);
                float v = acc[fm][fn][q] + bias[n];
                if (EPI == 1) Ch[(size_t)m*ldc + coff + n] = __float2half(gelu_f(v));
                else          C [(size_t)m*ldc + coff + n] = v;
            }
        }
    }
}

// =================== fused attention: score + softmax + aw write + AV ===================
#define SLD 516

__global__ void __launch_bounds__(256,1) fattn_k(
    const float* __restrict__ q1, const float* __restrict__ k1, const float* __restrict__ v1,
    const float* __restrict__ q2, const float* __restrict__ k2, const float* __restrict__ v2,
    const float* __restrict__ mask, const float* __restrict__ adjoin, const float* __restrict__ dist,
    float* __restrict__ aw_l, float* __restrict__ aw_g,
    __half* __restrict__ av1, __half* __restrict__ av2)
{
    extern __shared__ char smem_raw[];
    float* sL = (float*)smem_raw;                                        // [64][SLD]
    unsigned (*sQ)[68]  = (unsigned(*)[68]) (smem_raw + 64*SLD*4);       // [64][68]
    unsigned (*sB)[136] = (unsigned(*)[136])(smem_raw + 64*SLD*4 + 64*68*4); // [2*16][136]

    const int tid = threadIdx.x, lane = tid & 31, warp = tid >> 5;
    const int lg = lane >> 2, lt = lane & 3;
    const int zi = blockIdx.y;
    const int sel = zi >> 7, zb = zi & 127;
    const int b = zb >> 3, h = zb & 7;
    const int m0 = blockIdx.x * 64;

    const float* q  = (sel ? q2 : q1) + (size_t)zb*Sn*HDn;
    const float* kT = (sel ? k2 : k1) + (size_t)zb*HDn*Sn;
    const float* v  = (sel ? v2 : v1) + (size_t)zb*Sn*HDn;
    float* aw = (sel ? aw_g : aw_l) + (size_t)zb*Sn*Sn;
    __half* av = sel ? av2 : av1;
    const float* extra = (sel ? dist : adjoin) + (size_t)b*Sn*Sn;
    const float* mrow  = mask + (size_t)b*Sn;

    #pragma unroll
    for (int it = 0; it < 4; it++) {
        int l = tid + it*256;
        int row = l >> 4, dq = l & 15;
        float4 a = *(const float4*)(q + (size_t)(m0+row)*HDn + dq*4);
        uint4 t;
        t.x = f2tf(a.x); t.y = f2tf(a.y); t.z = f2tf(a.z); t.w = f2tf(a.w);
        *(uint4*)(&sQ[row][dq*4]) = t;
    }

    {
        const int wy = warp >> 2, wx = warp & 3;
        const int bkk = tid >> 5, bnq = tid & 31;
        for (int n0b = 0; n0b < 512; n0b += 128) {
            float acc[2][4][4];
            #pragma unroll
            for (int i=0;i<2;i++) for (int j=0;j<4;j++) for (int r=0;r<4;r++) acc[i][j][r]=0.f;

            float4 rk[2];
            #pragma unroll
            for (int it = 0; it < 2; it++)
                rk[it] = *(const float4*)(kT + (size_t)(bkk + it*8)*Sn + n0b + bnq*4);
            #pragma unroll
            for (int it = 0; it < 2; it++) {
                uint4 t;
                t.x = f2tf(rk[it].x); t.y = f2tf(rk[it].y);
                t.z = f2tf(rk[it].z); t.w = f2tf(rk[it].w);
                *(uint4*)(&sB[bkk + it*8][bnq*4]) = t;
            }
            __syncthreads();

            for (int kc = 0; kc < 4; kc++) {
                const int cur = kc & 1;
                if (kc < 3) {
                    #pragma unroll
                    for (int it = 0; it < 2; it++)
                        rk[it] = *(const float4*)(kT + (size_t)(kc*16 + 16 + bkk + it*8)*Sn + n0b + bnq*4);
                }
                unsigned (*Bc)[136] = sB + cur*16;
                #pragma unroll
                for (int ks = 0; ks < 2; ks++) {
                    int kb = kc*16 + ks*8;
                    int sbm = ks*8;
                    unsigned af[2][4], bf[4][2];
                    #pragma unroll
                    for (int fm = 0; fm < 2; fm++) {
                        int rb = wy*32 + fm*16 + lg;
                        af[fm][0] = sQ[rb  ][kb+lt];
                        af[fm][1] = sQ[rb+8][kb+lt];
                        af[fm][2] = sQ[rb  ][kb+4+lt];
                        af[fm][3] = sQ[rb+8][kb+4+lt];
                    }
                    #pragma unroll
                    for (int fn = 0; fn < 4; fn++) {
                        int cb = wx*32 + fn*8 + lg;
                        bf[fn][0] = Bc[sbm+lt  ][cb];
                        bf[fn][1] = Bc[sbm+4+lt][cb];
                    }
                    #pragma unroll
                    for (int fm = 0; fm < 2; fm++)
                        #pragma unroll
                        for (int fn = 0; fn < 4; fn++)
                            MMA_TF32(acc[fm][fn], af[fm], bf[fn]);
                }
                if (kc < 3) {
                    unsigned (*Bnx)[136] = sB + (1-cur)*16;
                    #pragma unroll
                    for (int it = 0; it < 2; it++) {
                        uint4 t;
                        t.x = f2tf(rk[it].x); t.y = f2tf(rk[it].y);
                        t.z = f2tf(rk[it].z); t.w = f2tf(rk[it].w);
                        *(uint4*)(&Bnx[bkk + it*8][bnq*4]) = t;
                    }
                }
                __syncthreads();
            }
            #pragma unroll
            for (int fm = 0; fm < 2; fm++) {
                #pragma unroll
                for (int fn = 0; fn < 4; fn++) {
                    #pragma unroll
                    for (int q4 = 0; q4 < 4; q4++) {
                        int r = wy*32 + fm*16 + lg + ((q4>=2) ? 8 : 0);
                        int c = wx*32 + fn*8 + lt*2 + (q4&1);
                        int j = n0b + c;
                        float s = acc[fm][fn][q4];
                        float logit;
                        if (sel == 0) {
                            logit = s*0.125f + mrow[j]*(-1.0e9f)
                                  + extra[(size_t)(m0+r)*Sn + j];
                        } else {
                            float w  = extra[(size_t)(m0+r)*Sn + j];
                            float rs = 3.7182818284590452f / (1.f + expf(1.f - w));
                            logit = fmaxf(s, 0.f)*rs*0.125f + mrow[j]*(-1.0e9f);
                        }
                        sL[r*SLD + j] = logit;
                    }
                }
            }
        }
    }
    __syncthreads();

    for (int rr = 0; rr < 8; rr++) {
        int r = warp*8 + rr;
        float4* rowp = (float4*)(sL + (size_t)r*SLD);
        float4 rv[4];
        float lmax = -3.0e38f;
        #pragma unroll
        for (int it = 0; it < 4; it++) {
            float4 v4 = rowp[it*32 + lane];
            rv[it] = v4;
            lmax = fmaxf(lmax, fmaxf(fmaxf(v4.x, v4.y), fmaxf(v4.z, v4.w)));
        }
        #pragma unroll
        for (int o = 16; o > 0; o >>= 1)
            lmax = fmaxf(lmax, __shfl_xor_sync(0xffffffffu, lmax, o));
        float sum = 0.f;
        #pragma unroll
        for (int it = 0; it < 4; it++) {
            rv[it].x = expf(rv[it].x - lmax);
            rv[it].y = expf(rv[it].y - lmax);
            rv[it].z = expf(rv[it].z - lmax);
            rv[it].w = expf(rv[it].w - lmax);
            sum += rv[it].x + rv[it].y + rv[it].z + rv[it].w;
        }
        #pragma unroll
        for (int o = 16; o > 0; o >>= 1)
            sum += __shfl_xor_sync(0xffffffffu, sum, o);
        float inv = 1.f / sum;
        float4* awp = (float4*)(aw + (size_t)(m0+r)*Sn);
        #pragma unroll
        for (int it = 0; it < 4; it++) {
            rv[it].x *= inv; rv[it].y *= inv; rv[it].z *= inv; rv[it].w *= inv;
            rowp[it*32 + lane] = rv[it];
            awp[it*32 + lane]  = rv[it];
        }
    }
    __syncthreads();

    {
        const int wy4 = warp >> 1, wx4 = warp & 1;
        const int vkk = tid >> 4, vdq = tid & 15;
        float acc2[4][4];
        #pragma unroll
        for (int j=0;j<4;j++) for (int r=0;r<4;r++) acc2[j][r]=0.f;

        float4 rvv;
        rvv = *(const float4*)(v + (size_t)vkk*HDn + vdq*4);
        {
            uint4 t;
            t.x = f2tf(rvv.x); t.y = f2tf(rvv.y); t.z = f2tf(rvv.z); t.w = f2tf(rvv.w);
            *(uint4*)(&sB[vkk][vdq*4]) = t;
        }
        __syncthreads();

        for (int kc = 0; kc < 32; kc++) {
            const int cur = kc & 1;
            if (kc < 31)
                rvv = *(const float4*)(v + (size_t)(kc*16 + 16 + vkk)*HDn + vdq*4);

            unsigned (*Bc)[136] = sB + cur*16;
            #pragma unroll
            for (int ks = 0; ks < 2; ks++) {
                int kb = kc*16 + ks*8;
                int sbm = ks*8;
                int rb = wy4*16 + lg;
                unsigned af[4];
                af[0] = f2tf(sL[(size_t) rb   *SLD + kb+lt]);
                af[1] = f2tf(sL[(size_t)(rb+8)*SLD + kb+lt]);
                af[2] = f2tf(sL[(size_t) rb   *SLD + kb+4+lt]);
                af[3] = f2tf(sL[(size_t)(rb+8)*SLD + kb+4+lt]);
                unsigned bf[4][2];
                #pragma unroll
                for (int fn = 0; fn < 4; fn++) {
                    int cb = wx4*32 + fn*8 + lg;
                    bf[fn][0] = Bc[sbm+lt  ][cb];
                    bf[fn][1] = Bc[sbm+4+lt][cb];
                }
                #pragma unroll
                for (int fn = 0; fn < 4; fn++)
                    MMA_TF32(acc2[fn], af, bf[fn]);
            }
            if (kc < 31) {
                unsigned (*Bnx)[136] = sB + (1-cur)*16;
                uint4 t;
                t.x = f2tf(rvv.x); t.y = f2tf(rvv.y); t.z = f2tf(rvv.z); t.w = f2tf(rvv.w);
                *(uint4*)(&Bnx[vkk][vdq*4]) = t;
            }
            __syncthreads();
        }
        #pragma unroll
        for (int fn = 0; fn < 4; fn++) {
            #pragma unroll
            for (int q4 = 0; q4 < 4; q4++) {
                int r = wy4*16 + lg + ((q4>=2) ? 8 : 0);
                int c = wx4*32 + fn*8 + lt*2 + (q4&1);
                av[((size_t)b*Sn + m0 + r)*DHn + h*HDn + c] = __float2half(acc2[fn][q4]);
            }
        }
    }
}

// ---------------- fused add + LayerNorm (optional half copy) ----------------
__global__ void __launch_bounds__(256) add_ln_k(
    const float* __restrict__ a, const float* __restrict__ r,
    const float* __restrict__ g, const float* __restrict__ be,
    float* __restrict__ out, __half* __restrict__ outr)
{
    __shared__ float red[8];
    const int row = blockIdx.x;
    const int t = threadIdx.x;
    const float* ar = a + (size_t)row*Dn;
    const float* rr = r + (size_t)row*Dn;

    float vals[4];
    float s = 0.f;
    #pragma unroll
    for (int c=0;c<4;c++){
        float x = ar[t + c*256] + rr[t + c*256];
        vals[c] = x; s += x;
    }
    #pragma unroll
    for (int o=16;o>0;o>>=1) s += __shfl_xor_sync(0xffffffffu, s, o);
    if ((t & 31) == 0) red[t>>5] = s;
    __syncthreads();
    float tot = 0.f;
    #pragma unroll
    for (int w=0;w<8;w++) tot += red[w];
    float mean = tot * (1.f/1024.f);
    __syncthreads();

    float sq = 0.f;
    #pragma unroll
    for (int c=0;c<4;c++){ float dx = vals[c]-mean; sq += dx*dx; }
    #pragma unroll
    for (int o=16;o>0;o>>=1) sq += __shfl_xor_sync(0xffffffffu, sq, o);
    if ((t & 31) == 0) red[t>>5] = sq;
    __syncthreads();
    float vtot = 0.f;
    #pragma unroll
    for (int w=0;w<8;w++) vtot += red[w];
    float invstd = rsqrtf(vtot*(1.f/1024.f) + 1e-5f);

    #pragma unroll
    for (int c=0;c<4;c++){
        int dd = t + c*256;
        float o = (vals[c]-mean)*invstd*g[dd] + be[dd];
        out[(size_t)row*Dn + dd] = o;
        if (outr) outr[(size_t)row*Dn + dd] = __float2half(o);
    }
}

// ---------------- launch ----------------
#define FATTN_SMEM (64*SLD*4 + 64*68*4 + 2*16*136*4)

extern "C" void kernel_launch(void* const* d_in, const int* in_sizes, int n_in,
                              void* d_out, int out_size)
{
    const float* x      = (const float*)d_in[0];
    const float* mask   = (const float*)d_in[2];
    const float* adjoin = (const float*)d_in[3];
    const float* dist   = (const float*)d_in[4];
    const float* wq1=(const float*)d_in[5],  *bq1=(const float*)d_in[6];
    const float* wk1=(const float*)d_in[7],  *bk1=(const float*)d_in[8];
    const float* wv1=(const float*)d_in[9],  *bv1=(const float*)d_in[10];
    const float* wo1=(const float*)d_in[11], *bo1=(const float*)d_in[12];
    const float* wq2=(const float*)d_in[13], *bq2=(const float*)d_in[14];
    const float* wk2=(const float*)d_in[15], *bk2=(const float*)d_in[16];
    const float* wv2=(const float*)d_in[17], *bv2=(const float*)d_in[18];
    const float* wo2=(const float*)d_in[19], *bo2=(const float*)d_in[20];
    const float* wff1=(const float*)d_in[21], *bff1=(const float*)d_in[22];
    const float* wff2=(const float*)d_in[23], *bff2=(const float*)d_in[24];
    const float* ln1g=(const float*)d_in[25], *ln1b=(const float*)d_in[26];
    const float* ln2g=(const float*)d_in[27], *ln2b=(const float*)d_in[28];

    float* out2 = (float*)d_out;                         // (B,S,D)
    float* aw_l = out2 + (size_t)BSn*Dn;                 // (B,H,S,S)
    float* aw_g = aw_l + (size_t)Bn*Hn*Sn*Sn;            // (B,H,S,S)

    float *q1,*k1,*v1,*q2,*k2,*v2,*attn,*out1,*ffn;
    __half *av1,*av2,*out1r,*hid,*xr,*wt;
    cudaGetSymbolAddress((void**)&q1, g_q1);
    cudaGetSymbolAddress((void**)&k1, g_k1);
    cudaGetSymbolAddress((void**)&v1, g_v1);
    cudaGetSymbolAddress((void**)&q2, g_q2);
    cudaGetSymbolAddress((void**)&k2, g_k2);
    cudaGetSymbolAddress((void**)&v2, g_v2);
    cudaGetSymbolAddress((void**)&av1, g_av1);
    cudaGetSymbolAddress((void**)&av2, g_av2);
    cudaGetSymbolAddress((void**)&attn, g_attn);
    cudaGetSymbolAddress((void**)&out1, g_out1);
    cudaGetSymbolAddress((void**)&out1r, g_out1r);
    cudaGetSymbolAddress((void**)&hid, g_hid);
    cudaGetSymbolAddress((void**)&ffn, g_ffn);
    cudaGetSymbolAddress((void**)&xr, g_xr);
    cudaGetSymbolAddress((void**)&wt, g_wt);

    static int smem_set = 0;
    if (!smem_set) {
        cudaFuncSetAttribute(fattn_k, cudaFuncAttributeMaxDynamicSharedMemorySize, FATTN_SMEM);
        cudaFuncSetAttribute(qkv_k,    cudaFuncAttributeMaxDynamicSharedMemorySize, G2_SMEM);
        cudaFuncSetAttribute(lin_k<0>, cudaFuncAttributeMaxDynamicSharedMemorySize, G2_SMEM);
        cudaFuncSetAttribute(lin_k<1>, cudaFuncAttributeMaxDynamicSharedMemorySize, G2_SMEM);
        smem_set = 1;
    }

    // ---- prep: convert x; transpose+convert all weights ----
    round_k<<<512,256>>>(x, xr, BSn*Dn);
    trp8_k<<<dim3(16,16,8), dim3(32,8)>>>(wq1,wk1,wv1,wq2,wk2,wv2,wo1,wo2, wt);
    trp_k<<<dim3(128,32), dim3(32,8)>>>(wff1, wt + WT_FF1, 1024, 4096);   // -> [4096][1024]
    trp_k<<<dim3(32,128), dim3(32,8)>>>(wff2, wt + WT_FF2, 4096, 1024);   // -> [1024][4096]

    // ---- QKV: 6 fused batched GEMMs (K stored transposed) ----
    dim3 gqkv(4, 64, 6);
    qkv_k<<<gqkv,256,G2_SMEM>>>(xr, wt, bq1,bk1,bv1,bq2,bk2,bv2,
                                q1,k1,v1,q2,k2,v2);

    // ---- fused attention ----
    dim3 gfa(8, 256);
    fattn_k<<<gfa,256,FATTN_SMEM>>>(q1,k1,v1, q2,k2,v2,
                                    mask, adjoin, dist,
                                    aw_l, aw_g, av1, av2);

    // ---- output projections -> concat into g_attn ----
    dim3 gop(4, 64);
    lin_k<0><<<gop,256,G2_SMEM>>>(av1, DHn, wt + 6*262144, DHn, bo1, attn, (__half*)0, Dn, 0);
    lin_k<0><<<gop,256,G2_SMEM>>>(av2, DHn, wt + 7*262144, DHn, bo2, attn, (__half*)0, Dn, DHn);

    // ---- LN1(x + attn) -> out1 (+ half copy) ----
    add_ln_k<<<BSn,256>>>(x, attn, ln1g, ln1b, out1, out1r);

    // ---- FFN ----
    dim3 gff1(32, 64);
    lin_k<1><<<gff1,256,G2_SMEM>>>(out1r, Dn, wt + WT_FF1, Dn, bff1, (float*)0, hid, DFFn, 0);
    dim3 gff2(8, 64);
    lin_k<0><<<gff2,256,G2_SMEM>>>(hid, DFFn, wt + WT_FF2, DFFn, bff2, ffn, (__half*)0, Dn, 0);

    // ---- LN2(out1 + ffn) -> out2 ----
    add_ln_k<<<BSn,256>>>(out1, ffn, ln2g, ln2b, out2, (__half*)0);
}

// round 14
// speedup vs baseline: 1.6804x; 1.2101x over previous
#include <cuda_runtime.h>
#include <cuda_fp16.h>
#include <math.h>
#include <stdint.h>

#define Bn   16
#define Sn   512
#define Dn   1024
#define Hn   8
#define DHn  512
#define HDn  64
#define DFFn 4096
#define BSn  (Bn*Sn)   // 8192

// ---------------- scratch (static device globals; no allocation) ----------------
__device__ __half g_q1[Bn*Hn*Sn*HDn];   // (B,H,S,64) half
__device__ __half g_k1[Bn*Hn*Sn*HDn];
__device__ __half g_v1[Bn*Hn*Sn*HDn];
__device__ __half g_q2[Bn*Hn*Sn*HDn];
__device__ __half g_k2[Bn*Hn*Sn*HDn];
__device__ __half g_v2[Bn*Hn*Sn*HDn];
__device__ __half g_av1[BSn*DHn];
__device__ __half g_av2[BSn*DHn];
__device__ float g_attn[BSn*Dn];
__device__ float g_out1[BSn*Dn];
__device__ __half g_out1r[BSn*Dn];
__device__ __half g_hid[(size_t)BSn*DFFn];
__device__ float g_ffn[BSn*Dn];
__device__ __half g_xr[BSn*Dn];
#define WT_FF1 2097152
#define WT_FF2 (2097152 + 4194304)
__device__ __half g_wt[WT_FF2 + 4194304];

__device__ __forceinline__ float gelu_f(float x){
    return 0.5f * x * (1.0f + erff(x * 0.70710678118654752440f));
}
__device__ __forceinline__ uint32_t smem_u32(const void* p){
    uint32_t a;
    asm("{ .reg .u64 t; cvta.to.shared.u64 t, %1; cvt.u32.u64 %0, t; }" : "=r"(a) : "l"(p));
    return a;
}

#define MMA_F16(acc, af, bf) \
    asm volatile( \
        "mma.sync.aligned.m16n8k16.row.col.f32.f16.f16.f32 " \
        "{%0,%1,%2,%3}, {%4,%5,%6,%7}, {%8,%9}, {%0,%1,%2,%3};" \
        : "+f"((acc)[0]), "+f"((acc)[1]), "+f"((acc)[2]), "+f"((acc)[3]) \
        : "r"((af)[0]), "r"((af)[1]), "r"((af)[2]), "r"((af)[3]), \
          "r"((bf)[0]), "r"((bf)[1]))

#define CP16(d, s) asm volatile("cp.async.cg.shared.global [%0], [%1], 16;" :: "r"(d), "l"(s))
#define CPCOMMIT() asm volatile("cp.async.commit_group;" ::: "memory")
#define CPWAIT2()  asm volatile("cp.async.wait_group 2;" ::: "memory")
#define CPWAIT0()  asm volatile("cp.async.wait_group 0;" ::: "memory")
#define LDSM4(r, a) \
    asm volatile("ldmatrix.sync.aligned.m8n8.x4.shared.b16 {%0,%1,%2,%3}, [%4];" \
        : "=r"((r)[0]), "=r"((r)[1]), "=r"((r)[2]), "=r"((r)[3]) : "r"(a))
#define LDSM4T(r, a) \
    asm volatile("ldmatrix.sync.aligned.m8n8.x4.trans.shared.b16 {%0,%1,%2,%3}, [%4];" \
        : "=r"((r)[0]), "=r"((r)[1]), "=r"((r)[2]), "=r"((r)[3]) : "r"(a))

// =================== cp.async + ldmatrix pipelined FP16 GEMM core ===================
#define NS   4
#define STGA 10240
#define STG  (2*STGA)
#define G2_SMEM (NS*STG)

__device__ __forceinline__ void core_pipe_h(
    const __half* __restrict__ A, int lda,
    const __half* __restrict__ Bt, int ldbt,
    int K, char* smc, float (&acc)[4][4][4])
{
    const int tid = threadIdx.x, lane = tid & 31, warp = tid >> 5;
    const int wy = warp >> 2, wx = warp & 3;
    const uint32_t sb = smem_u32(smc);
    const int lrow = lane & 15;
    const int lc16 = (lane >> 4) & 1;
    const int crow = tid >> 2, ccol = tid & 3;

    const int nslab = K >> 5;
    #pragma unroll
    for (int s = 0; s < NS-1; s++){
        if (s < nslab){
            const int k0 = s << 5;
            uint32_t stA = sb + s*STG;
            uint32_t stB = stA + STGA;
            #pragma unroll
            for (int it = 0; it < 2; it++){
                int r = crow + it*64;
                CP16(stA + r*80 + ccol*16, A  + (size_t)r*lda  + k0 + ccol*8);
                CP16(stB + r*80 + ccol*16, Bt + (size_t)r*ldbt + k0 + ccol*8);
            }
        }
        CPCOMMIT();
    }

    for (int s = 0; s < nslab; s++){
        CPWAIT2();
        __syncthreads();
        {
            int nx = s + NS-1;
            if (nx < nslab){
                const int k0 = nx << 5;
                uint32_t stA = sb + (nx & (NS-1))*STG;
                uint32_t stB = stA + STGA;
                #pragma unroll
                for (int it = 0; it < 2; it++){
                    int r = crow + it*64;
                    CP16(stA + r*80 + ccol*16, A  + (size_t)r*lda  + k0 + ccol*8);
                    CP16(stB + r*80 + ccol*16, Bt + (size_t)r*ldbt + k0 + ccol*8);
                }
            }
            CPCOMMIT();
        }
        uint32_t aA = sb + (s & (NS-1))*STG;
        uint32_t aB = aA + STGA;
        #pragma unroll
        for (int ks = 0; ks < 2; ks++){
            unsigned af[4][4], bq[2][4];
            #pragma unroll
            for (int fm = 0; fm < 4; fm++){
                uint32_t ad = aA + (uint32_t)((wy*64 + fm*16 + lrow)*80 + ks*32 + lc16*16);
                LDSM4(af[fm], ad);
            }
            #pragma unroll
            for (int p = 0; p < 2; p++){
                uint32_t ad = aB + (uint32_t)((wx*32 + p*16 + lrow)*80 + ks*32 + lc16*16);
                LDSM4(bq[p], ad);
            }
            #pragma unroll
            for (int fm = 0; fm < 4; fm++){
                #pragma unroll
                for (int p = 0; p < 2; p++){
                    unsigned b0[2] = { bq[p][0], bq[p][2] };
                    unsigned b1[2] = { bq[p][1], bq[p][3] };
                    MMA_F16(acc[fm][2*p],   af[fm], b0);
                    MMA_F16(acc[fm][2*p+1], af[fm], b1);
                }
            }
        }
    }
}

// =================== prep ===================
__global__ void round_k(const float* __restrict__ s, __half* __restrict__ d, int n){
    int i = blockIdx.x*blockDim.x + threadIdx.x;
    int st = gridDim.x*blockDim.x;
    for (; i < n; i += st) d[i] = __float2half(s[i]);
}

__global__ void trp_k(const float* __restrict__ src, __half* __restrict__ dst, int R, int C){
    __shared__ float t[32][33];
    int cx = blockIdx.x*32, cy = blockIdx.y*32;
    int tx = threadIdx.x, ty = threadIdx.y;
    #pragma unroll
    for (int i = 0; i < 4; i++)
        t[ty + i*8][tx] = src[(size_t)(cy + ty + i*8)*C + cx + tx];
    __syncthreads();
    #pragma unroll
    for (int i = 0; i < 4; i++)
        dst[(size_t)(cx + ty + i*8)*R + cy + tx] = __float2half(t[tx][ty + i*8]);
}

__global__ void trp8_k(const float* w0, const float* w1, const float* w2, const float* w3,
                       const float* w4, const float* w5, const float* w6, const float* w7,
                       __half* __restrict__ dst)
{
    __shared__ float t[32][33];
    const float* src;
    switch (blockIdx.z){
        case 0: src=w0; break; case 1: src=w1; break; case 2: src=w2; break; case 3: src=w3; break;
        case 4: src=w4; break; case 5: src=w5; break; case 6: src=w6; break; default: src=w7; break;
    }
    __half* d = dst + (size_t)blockIdx.z*262144;
    int cx = blockIdx.x*32, cy = blockIdx.y*32;
    int tx = threadIdx.x, ty = threadIdx.y;
    #pragma unroll
    for (int i = 0; i < 4; i++)
        t[ty + i*8][tx] = src[(size_t)(cy + ty + i*8)*512 + cx + tx];
    __syncthreads();
    #pragma unroll
    for (int i = 0; i < 4; i++)
        d[(size_t)(cx + ty + i*8)*512 + cy + tx] = __float2half(t[tx][ty + i*8]);
}

// =================== QKV: 6 batched GEMMs, (B,H,S,64) half outputs ===================
__global__ void __launch_bounds__(256,2) qkv_k(
    const __half* __restrict__ xr, const __half* __restrict__ wt,
    const float* b0, const float* b1, const float* b2,
    const float* b3, const float* b4, const float* b5,
    __half* o0, __half* o1, __half* o2, __half* o3, __half* o4, __half* o5)
{
    extern __shared__ char smc[];
    const int z = blockIdx.z;
    const float* bi; __half* dst;
    switch (z) {
        case 0: bi=b0; dst=o0; break;
        case 1: bi=b1; dst=o1; break;
        case 2: bi=b2; dst=o2; break;
        case 3: bi=b3; dst=o3; break;
        case 4: bi=b4; dst=o4; break;
        default:bi=b5; dst=o5; break;
    }
    const int m0 = blockIdx.y*128, n0 = blockIdx.x*128;
    const __half* A  = xr + (z>=3 ? DHn : 0) + (size_t)m0*Dn;
    const __half* Bt = wt + (size_t)z*262144 + (size_t)n0*DHn;

    float acc[4][4][4];
    #pragma unroll
    for (int i=0;i<4;i++) for (int j=0;j<4;j++) for (int r=0;r<4;r++) acc[i][j][r]=0.f;

    core_pipe_h(A, Dn, Bt, DHn, DHn, smc, acc);

    const int lane = threadIdx.x & 31, warp = threadIdx.x >> 5;
    const int wy = warp >> 2, wx = warp & 3;
    const int lg = lane >> 2, lt = lane & 3;

    #pragma unroll
    for (int fm=0; fm<4; fm++){
        #pragma unroll
        for (int fn=0; fn<4; fn++){
            int r = wy*64 + fm*16 + lg;
            int c = wx*32 + fn*8 + lt*2;
            #pragma unroll
            for (int qp=0; qp<4; qp+=2){
                int m = m0 + r + (qp ? 8 : 0);
                int n = n0 + c;
                float v0 = acc[fm][fn][qp]   + bi[n];
                float v1 = acc[fm][fn][qp+1] + bi[n+1];
                int b = m>>9, s = m&511, h = n>>6, d = n&63;
                *(__half2*)(dst + (((size_t)(b*8+h))*512 + s)*64 + d) =
                    __floats2half2_rn(v0, v1);
            }
        }
    }
}

// =================== generic linear (pipelined) ===================
template<int EPI>
__global__ void __launch_bounds__(256,2) lin_k(
    const __half* __restrict__ A, int lda,
    const __half* __restrict__ Bt, int K,
    const float* __restrict__ bias,
    float* __restrict__ C, __half* __restrict__ Ch, int ldc, int coff)
{
    extern __shared__ char smc[];
    const int m0 = blockIdx.y*128, n0 = blockIdx.x*128;
    const __half* Ap  = A  + (size_t)m0*lda;
    const __half* Btp = Bt + (size_t)n0*K;

    float acc[4][4][4];
    #pragma unroll
    for (int i=0;i<4;i++) for (int j=0;j<4;j++) for (int r=0;r<4;r++) acc[i][j][r]=0.f;

    core_pipe_h(Ap, lda, Btp, K, K, smc, acc);

    const int lane = threadIdx.x & 31, warp = threadIdx.x >> 5;
    const int wy = warp >> 2, wx = warp & 3;
    const int lg = lane >> 2, lt = lane & 3;

    #pragma unroll
    for (int fm=0; fm<4; fm++){
        #pragma unroll
        for (int fn=0; fn<4; fn++){
            int r = wy*64 + fm*16 + lg;
            int c = wx*32 + fn*8 + lt*2;
            #pragma unroll
            for (int q=0; q<4; q++){
                int m = m0 + r + (q>=2 ? 8 : 0);
                int n = n0 + c + (q&1);
                float v = acc[fm][fn][q] + bias[n];
                if (EPI == 1) Ch[(size_t)m*ldc + coff + n] = __float2half(gelu_f(v));
                else          C [(size_t)m*ldc + coff + n] = v;
            }
        }
    }
}

// =================== fused attention (fp16 tensor cores) ===================
// smem: sL fp32 [64][516] (logits; first 1024B of each row reused as half probs)
//       sQ half [64 rows][144B stride]
//       sKV half double-buffered [2][128 rows][144B stride]
#define SLD  516
#define SLDB 2064
#define SQ_OFF   132096
#define SKV_OFF  (132096 + 9216)
#define KVBUF    18432
#define FATTN_SMEM (SKV_OFF + 2*KVBUF)   // 178176

__global__ void __launch_bounds__(256,1) fattn_k(
    const __half* __restrict__ q1, const __half* __restrict__ k1, const __half* __restrict__ v1,
    const __half* __restrict__ q2, const __half* __restrict__ k2, const __half* __restrict__ v2,
    const float* __restrict__ mask, const float* __restrict__ adjoin, const float* __restrict__ dist,
    float* __restrict__ aw_l, float* __restrict__ aw_g,
    __half* __restrict__ av1, __half* __restrict__ av2)
{
    extern __shared__ char smem_raw[];
    float* sL = (float*)smem_raw;
    char*  sQc = smem_raw + SQ_OFF;
    const uint32_t sLb  = smem_u32(smem_raw);
    const uint32_t sQb  = sLb + SQ_OFF;
    const uint32_t kvb  = sLb + SKV_OFF;

    const int tid = threadIdx.x, lane = tid & 31, warp = tid >> 5;
    const int lg = lane >> 2, lt = lane & 3;
    const int lrow = lane & 15, lc16 = (lane >> 4) & 1;
    const int zi = blockIdx.y;
    const int sel = zi >> 7, zb = zi & 127;
    const int b = zb >> 3, h = zb & 7;
    const int m0 = blockIdx.x * 64;

    const __half* q  = (sel ? q2 : q1) + (size_t)zb*Sn*HDn;
    const __half* kh = (sel ? k2 : k1) + (size_t)zb*Sn*HDn;
    const __half* vh = (sel ? v2 : v1) + (size_t)zb*Sn*HDn;
    float* aw = (sel ? aw_g : aw_l) + (size_t)zb*Sn*Sn;
    __half* av = sel ? av2 : av1;
    const float* extra = (sel ? dist : adjoin) + (size_t)b*Sn*Sn;
    const float* mrow  = mask + (size_t)b*Sn;

    // ---- Phase 1: Q tile (64x64 half) -> sQ ----
    #pragma unroll
    for (int i2 = 0; i2 < 2; i2++){
        int idx = tid + i2*256;
        int row = idx >> 3, ch = idx & 7;
        *(uint4*)(sQc + row*144 + ch*16) =
            *(const uint4*)(q + (size_t)(m0+row)*HDn + ch*8);
    }

    // ---- Phase 2: scores (fp16 mma), logits -> sL ----
    {
        const int wy = warp >> 2, wx = warp & 3;
        // prologue: stage keys [0,128) into buf0
        #pragma unroll
        for (int i2 = 0; i2 < 4; i2++){
            int idx = tid + i2*256;
            int row = idx >> 3, ch = idx & 7;
            CP16(kvb + row*144 + ch*16, kh + (size_t)row*HDn + ch*8);
        }
        CPCOMMIT();

        for (int it = 0; it < 4; it++){
            CPWAIT0();
            __syncthreads();
            if (it < 3){
                uint32_t dstb = kvb + ((it+1)&1)*KVBUF;
                const __half* src = kh + (size_t)(it+1)*128*HDn;
                #pragma unroll
                for (int i2 = 0; i2 < 4; i2++){
                    int idx = tid + i2*256;
                    int row = idx >> 3, ch = idx & 7;
                    CP16(dstb + row*144 + ch*16, src + (size_t)row*HDn + ch*8);
                }
                CPCOMMIT();
            }
            uint32_t bufb = kvb + (it&1)*KVBUF;
            float acc[2][4][4];
            #pragma unroll
            for (int i=0;i<2;i++) for (int j=0;j<4;j++) for (int r=0;r<4;r++) acc[i][j][r]=0.f;

            #pragma unroll
            for (int ks = 0; ks < 4; ks++){
                unsigned af[2][4], bq[2][4];
                #pragma unroll
                for (int fm = 0; fm < 2; fm++)
                    LDSM4(af[fm], sQb + (uint32_t)((wy*32 + fm*16 + lrow)*144 + ks*32 + lc16*16));
                #pragma unroll
                for (int p = 0; p < 2; p++)
                    LDSM4(bq[p], bufb + (uint32_t)((wx*32 + p*16 + lrow)*144 + ks*32 + lc16*16));
                #pragma unroll
                for (int fm = 0; fm < 2; fm++){
                    #pragma unroll
                    for (int p = 0; p < 2; p++){
                        unsigned b0[2] = { bq[p][0], bq[p][2] };
                        unsigned b1[2] = { bq[p][1], bq[p][3] };
                        MMA_F16(acc[fm][2*p],   af[fm], b0);
                        MMA_F16(acc[fm][2*p+1], af[fm], b1);
                    }
                }
            }
            // epilogue: logits -> sL (cols it*128 .. +127)
            const int n0b = it*128;
            #pragma unroll
            for (int fm = 0; fm < 2; fm++){
                #pragma unroll
                for (int fn = 0; fn < 4; fn++){
                    #pragma unroll
                    for (int q4 = 0; q4 < 4; q4++){
                        int r = wy*32 + fm*16 + lg + ((q4>=2) ? 8 : 0);
                        int c = wx*32 + fn*8 + lt*2 + (q4&1);
                        int j = n0b + c;
                        float s = acc[fm][fn][q4];
                        float logit;
                        if (sel == 0) {
                            logit = s*0.125f + mrow[j]*(-1.0e9f)
                                  + extra[(size_t)(m0+r)*Sn + j];
                        } else {
                            float w  = extra[(size_t)(m0+r)*Sn + j];
                            float rs = 3.7182818284590452f / (1.f + expf(1.f - w));
                            logit = fmaxf(s, 0.f)*rs*0.125f + mrow[j]*(-1.0e9f);
                        }
                        sL[r*SLD + j] = logit;
                    }
                }
            }
        }
    }
    __syncthreads();

    // ---- Phase 3: softmax; write aw fp32 + half probs into sL row heads ----
    for (int rr = 0; rr < 8; rr++){
        int r = warp*8 + rr;
        float4* rowp = (float4*)(sL + (size_t)r*SLD);
        float4 rv[4];
        float lmax = -3.0e38f;
        #pragma unroll
        for (int it = 0; it < 4; it++){
            float4 v4 = rowp[it*32 + lane];
            rv[it] = v4;
            lmax = fmaxf(lmax, fmaxf(fmaxf(v4.x, v4.y), fmaxf(v4.z, v4.w)));
        }
        #pragma unroll
        for (int o = 16; o > 0; o >>= 1)
            lmax = fmaxf(lmax, __shfl_xor_sync(0xffffffffu, lmax, o));
        float sum = 0.f;
        #pragma unroll
        for (int it = 0; it < 4; it++){
            rv[it].x = expf(rv[it].x - lmax);
            rv[it].y = expf(rv[it].y - lmax);
            rv[it].z = expf(rv[it].z - lmax);
            rv[it].w = expf(rv[it].w - lmax);
            sum += rv[it].x + rv[it].y + rv[it].z + rv[it].w;
        }
        #pragma unroll
        for (int o = 16; o > 0; o >>= 1)
            sum += __shfl_xor_sync(0xffffffffu, sum, o);
        float inv = 1.f / sum;
        float4* awp = (float4*)(aw + (size_t)(m0+r)*Sn);
        __half2* rh = (__half2*)((char*)sL + (size_t)r*SLDB);
        #pragma unroll
        for (int it = 0; it < 4; it++){
            rv[it].x *= inv; rv[it].y *= inv; rv[it].z *= inv; rv[it].w *= inv;
            awp[it*32 + lane] = rv[it];
            rh[(it*32 + lane)*2 + 0] = __floats2half2_rn(rv[it].x, rv[it].y);
            rh[(it*32 + lane)*2 + 1] = __floats2half2_rn(rv[it].z, rv[it].w);
        }
    }
    __syncthreads();

    // ---- Phase 4: AV (fp16 mma; A = half probs, B = V via ldmatrix.trans) ----
    {
        const int wy4 = warp >> 1, wx4 = warp & 1;
        float acc2[4][4];
        #pragma unroll
        for (int j=0;j<4;j++) for (int r=0;r<4;r++) acc2[j][r]=0.f;

        // prologue: stage V slab 0
        #pragma unroll
        for (int i2 = 0; i2 < 4; i2++){
            int idx = tid + i2*256;
            int row = idx >> 3, ch = idx & 7;
            CP16(kvb + row*144 + ch*16, vh + (size_t)row*HDn + ch*8);
        }
        CPCOMMIT();

        for (int sl = 0; sl < 4; sl++){
            CPWAIT0();
            __syncthreads();
            if (sl < 3){
                uint32_t dstb = kvb + ((sl+1)&1)*KVBUF;
                const __half* src = vh + (size_t)(sl+1)*128*HDn;
                #pragma unroll
                for (int i2 = 0; i2 < 4; i2++){
                    int idx = tid + i2*256;
                    int row = idx >> 3, ch = idx & 7;
                    CP16(dstb + row*144 + ch*16, src + (size_t)row*HDn + ch*8);
                }
                CPCOMMIT();
            }
            uint32_t bufb = kvb + (sl&1)*KVBUF;
            #pragma unroll
            for (int ksc = 0; ksc < 8; ksc++){
                unsigned af[4], bq[2][4];
                LDSM4(af, sLb + (uint32_t)((wy4*16 + lrow)*SLDB + sl*256 + ksc*32 + lc16*16));
                #pragma unroll
                for (int p = 0; p < 2; p++)
                    LDSM4T(bq[p], bufb + (uint32_t)((ksc*16 + lrow)*144 + wx4*64 + p*32 + lc16*16));
                #pragma unroll
                for (int p = 0; p < 2; p++){
                    unsigned b0[2] = { bq[p][0], bq[p][1] };
                    unsigned b1[2] = { bq[p][2], bq[p][3] };
                    MMA_F16(acc2[2*p],   af, b0);
                    MMA_F16(acc2[2*p+1], af, b1);
                }
            }
        }
        #pragma unroll
        for (int fn = 0; fn < 4; fn++){
            #pragma unroll
            for (int qp = 0; qp < 4; qp += 2){
                int r = wy4*16 + lg + (qp ? 8 : 0);
                int c = wx4*32 + fn*8 + lt*2;
                *(__half2*)(av + ((size_t)b*Sn + m0 + r)*DHn + h*HDn + c) =
                    __floats2half2_rn(acc2[fn][qp], acc2[fn][qp+1]);
            }
        }
    }
}

// ---------------- fused add + LayerNorm ----------------
__global__ void __launch_bounds__(256) add_ln_k(
    const float* __restrict__ a, const float* __restrict__ r,
    const float* __restrict__ g, const float* __restrict__ be,
    float* __restrict__ out, __half* __restrict__ outr)
{
    __shared__ float red[8];
    const int row = blockIdx.x;
    const int t = threadIdx.x;
    const float* ar = a + (size_t)row*Dn;
    const float* rr = r + (size_t)row*Dn;

    float vals[4];
    float s = 0.f;
    #pragma unroll
    for (int c=0;c<4;c++){
        float x = ar[t + c*256] + rr[t + c*256];
        vals[c] = x; s += x;
    }
    #pragma unroll
    for (int o=16;o>0;o>>=1) s += __shfl_xor_sync(0xffffffffu, s, o);
    if ((t & 31) == 0) red[t>>5] = s;
    __syncthreads();
    float tot = 0.f;
    #pragma unroll
    for (int w=0;w<8;w++) tot += red[w];
    float mean = tot * (1.f/1024.f);
    __syncthreads();

    float sq = 0.f;
    #pragma unroll
    for (int c=0;c<4;c++){ float dx = vals[c]-mean; sq += dx*dx; }
    #pragma unroll
    for (int o=16;o>0;o>>=1) sq += __shfl_xor_sync(0xffffffffu, sq, o);
    if ((t & 31) == 0) red[t>>5] = sq;
    __syncthreads();
    float vtot = 0.f;
    #pragma unroll
    for (int w=0;w<8;w++) vtot += red[w];
    float invstd = rsqrtf(vtot*(1.f/1024.f) + 1e-5f);

    #pragma unroll
    for (int c=0;c<4;c++){
        int dd = t + c*256;
        float o = (vals[c]-mean)*invstd*g[dd] + be[dd];
        out[(size_t)row*Dn + dd] = o;
        if (outr) outr[(size_t)row*Dn + dd] = __float2half(o);
    }
}

// ---------------- launch ----------------
extern "C" void kernel_launch(void* const* d_in, const int* in_sizes, int n_in,
                              void* d_out, int out_size)
{
    const float* x      = (const float*)d_in[0];
    const float* mask   = (const float*)d_in[2];
    const float* adjoin = (const float*)d_in[3];
    const float* dist   = (const float*)d_in[4];
    const float* wq1=(const float*)d_in[5],  *bq1=(const float*)d_in[6];
    const float* wk1=(const float*)d_in[7],  *bk1=(const float*)d_in[8];
    const float* wv1=(const float*)d_in[9],  *bv1=(const float*)d_in[10];
    const float* wo1=(const float*)d_in[11], *bo1=(const float*)d_in[12];
    const float* wq2=(const float*)d_in[13], *bq2=(const float*)d_in[14];
    const float* wk2=(const float*)d_in[15], *bk2=(const float*)d_in[16];
    const float* wv2=(const float*)d_in[17], *bv2=(const float*)d_in[18];
    const float* wo2=(const float*)d_in[19], *bo2=(const float*)d_in[20];
    const float* wff1=(const float*)d_in[21], *bff1=(const float*)d_in[22];
    const float* wff2=(const float*)d_in[23], *bff2=(const float*)d_in[24];
    const float* ln1g=(const float*)d_in[25], *ln1b=(const float*)d_in[26];
    const float* ln2g=(const float*)d_in[27], *ln2b=(const float*)d_in[28];

    float* out2 = (float*)d_out;
    float* aw_l = out2 + (size_t)BSn*Dn;
    float* aw_g = aw_l + (size_t)Bn*Hn*Sn*Sn;

    float *attn,*out1,*ffn;
    __half *q1,*k1,*v1,*q2,*k2,*v2,*av1,*av2,*out1r,*hid,*xr,*wt;
    cudaGetSymbolAddress((void**)&q1, g_q1);
    cudaGetSymbolAddress((void**)&k1, g_k1);
    cudaGetSymbolAddress((void**)&v1, g_v1);
    cudaGetSymbolAddress((void**)&q2, g_q2);
    cudaGetSymbolAddress((void**)&k2, g_k2);
    cudaGetSymbolAddress((void**)&v2, g_v2);
    cudaGetSymbolAddress((void**)&av1, g_av1);
    cudaGetSymbolAddress((void**)&av2, g_av2);
    cudaGetSymbolAddress((void**)&attn, g_attn);
    cudaGetSymbolAddress((void**)&out1, g_out1);
    cudaGetSymbolAddress((void**)&out1r, g_out1r);
    cudaGetSymbolAddress((void**)&hid, g_hid);
    cudaGetSymbolAddress((void**)&ffn, g_ffn);
    cudaGetSymbolAddress((void**)&xr, g_xr);
    cudaGetSymbolAddress((void**)&wt, g_wt);

    static int smem_set = 0;
    if (!smem_set) {
        cudaFuncSetAttribute(fattn_k, cudaFuncAttributeMaxDynamicSharedMemorySize, FATTN_SMEM);
        cudaFuncSetAttribute(qkv_k,    cudaFuncAttributeMaxDynamicSharedMemorySize, G2_SMEM);
        cudaFuncSetAttribute(lin_k<0>, cudaFuncAttributeMaxDynamicSharedMemorySize, G2_SMEM);
        cudaFuncSetAttribute(lin_k<1>, cudaFuncAttributeMaxDynamicSharedMemorySize, G2_SMEM);
        smem_set = 1;
    }

    // ---- prep ----
    round_k<<<512,256>>>(x, xr, BSn*Dn);
    trp8_k<<<dim3(16,16,8), dim3(32,8)>>>(wq1,wk1,wv1,wq2,wk2,wv2,wo1,wo2, wt);
    trp_k<<<dim3(128,32), dim3(32,8)>>>(wff1, wt + WT_FF1, 1024, 4096);
    trp_k<<<dim3(32,128), dim3(32,8)>>>(wff2, wt + WT_FF2, 4096, 1024);

    // ---- QKV ----
    dim3 gqkv(4, 64, 6);
    qkv_k<<<gqkv,256,G2_SMEM>>>(xr, wt, bq1,bk1,bv1,bq2,bk2,bv2,
                                q1,k1,v1,q2,k2,v2);

    // ---- fused attention ----
    dim3 gfa(8, 256);
    fattn_k<<<gfa,256,FATTN_SMEM>>>(q1,k1,v1, q2,k2,v2,
                                    mask, adjoin, dist,
                                    aw_l, aw_g, av1, av2);

    // ---- output projections ----
    dim3 gop(4, 64);
    lin_k<0><<<gop,256,G2_SMEM>>>(av1, DHn, wt + 6*262144, DHn, bo1, attn, (__half*)0, Dn, 0);
    lin_k<0><<<gop,256,G2_SMEM>>>(av2, DHn, wt + 7*262144, DHn, bo2, attn, (__half*)0, Dn, DHn);

    // ---- LN1 ----
    add_ln_k<<<BSn,256>>>(x, attn, ln1g, ln1b, out1, out1r);

    // ---- FFN ----
    dim3 gff1(32, 64);
    lin_k<1><<<gff1,256,G2_SMEM>>>(out1r, Dn, wt + WT_FF1, Dn, bff1, (float*)0, hid, DFFn, 0);
    dim3 gff2(8, 64);
    lin_k<0><<<gff2,256,G2_SMEM>>>(hid, DFFn, wt + WT_FF2, DFFn, bff2, ffn, (__half*)0, Dn, 0);

    // ---- LN2 ----
    add_ln_k<<<BSn,256>>>(out1, ffn, ln2g, ln2b, out2, (__half*)0);
}